// round 7
// baseline (speedup 1.0000x reference)
#include <cuda_runtime.h>

#define MAXN 50000
#define MAXE 1600000
#define H 64

// ---------------- device scratch (no allocation allowed) ----------------
__device__ float g_hA[MAXN * H];     // node embeddings ping
__device__ float g_hB[MAXN * H];     // node embeddings pong
__device__ float g_neigh[MAXN * H];  // neighbor-sum accumulator
__device__ int   g_cnt[MAXN];        // out-degree (segment counts over src)
__device__ float g_ec[H * 4];        // fused edge constants: per j {M1[0..2], c1}

// ---------------- zero scratch ----------------
__global__ void k_zero(int n64, int n) {
    int i = blockIdx.x * blockDim.x + threadIdx.x;
    if (i < n64) g_neigh[i] = 0.f;
    if (i < n)   g_cnt[i] = 0;
}

// ---------------- precompute fused edge constants ----------------
// a = relu(M1 @ ef + c1) where
//   M1 = Wa[:, :64] @ We            (64x3)
//   c1 = Wa[:, :64] @ be + Wa[:, 64:] @ vnf_mean + ba
__global__ void k_pre(const float* __restrict__ enc, const float* __restrict__ Wa,
                      const float* __restrict__ ba, const float* __restrict__ We,
                      const float* __restrict__ be) {
    __shared__ float vm[H];
    int j = threadIdx.x;  // 64 threads
    float s = 0.f;
    #pragma unroll
    for (int v = 0; v < 16; v++) s += enc[v * H + j];
    vm[j] = s * (1.f / 16.f);
    __syncthreads();
    const float* wr = Wa + j * 128;  // Wa row j, (H+DM)=128 wide
    float m0 = 0.f, m1 = 0.f, m2 = 0.f, c = ba[j];
    #pragma unroll 8
    for (int m = 0; m < H; m++) {
        float w = wr[m];
        m0 += w * We[m * 3 + 0];
        m1 += w * We[m * 3 + 1];
        m2 += w * We[m * 3 + 2];
        c  += w * be[m];
    }
    #pragma unroll 8
    for (int d = 0; d < H; d++) c += wr[H + d] * vm[d];
    ((float4*)g_ec)[j] = make_float4(m0, m1, m2, c);
}

// ---------------- node_fc: h = node_feats @ Wn.T + bn ----------------
__global__ void k_nodefc(const float* __restrict__ nf, const float* __restrict__ Wn,
                         const float* __restrict__ bn, int N_) {
    __shared__ float Ws[H * 3];
    __shared__ float bs[H];
    int t = threadIdx.x;
    if (t < H * 3) Ws[t] = Wn[t];
    if (t < H) bs[t] = bn[t];
    __syncthreads();
    int idx = blockIdx.x * blockDim.x + t;
    if (idx >= N_ * H) return;
    int n = idx >> 6, j = idx & 63;
    float f0 = nf[n * 3 + 0], f1 = nf[n * 3 + 1], f2 = nf[n * 3 + 2];
    g_hA[idx] = Ws[j * 3 + 0] * f0 + Ws[j * 3 + 1] * f1 + Ws[j * 3 + 2] * f2 + bs[j];
}

// ---------------- fused edge scorer + degree count ----------------
// score = b2 + w2 . relu(W1 @ relu(M1 @ ef + c1) + b1)
__global__ __launch_bounds__(128) void k_scorer(
    const float* __restrict__ ef, const int* __restrict__ src,
    const float* __restrict__ W1, const float* __restrict__ b1,
    const float* __restrict__ W2, const float* __restrict__ b2,
    float* __restrict__ out, int E_) {
    __shared__ float4 W1s[H * H / 4];  // 16 KB, row-major float4
    __shared__ float4 ECs[H];
    __shared__ float b1s[H], w2s[H];
    __shared__ float b2s;
    int t = threadIdx.x;
    for (int i = t; i < H * H / 4; i += blockDim.x) W1s[i] = ((const float4*)W1)[i];
    if (t < H) {
        ECs[t] = ((const float4*)g_ec)[t];
        b1s[t] = b1[t];
        w2s[t] = W2[t];
    }
    if (t == 0) b2s = b2[0];
    __syncthreads();

    int e = blockIdx.x * blockDim.x + t;
    if (e >= E_) return;

    // degree (segment count over src)
    atomicAdd(&g_cnt[src[e]], 1);

    float f0 = ef[e * 3 + 0], f1 = ef[e * 3 + 1], f2 = ef[e * 3 + 2];
    float a[H];
    #pragma unroll
    for (int j = 0; j < H; j++) {
        float4 m = ECs[j];
        a[j] = fmaxf(m.x * f0 + m.y * f1 + m.z * f2 + m.w, 0.f);
    }
    float score = b2s;
    #pragma unroll 4
    for (int i = 0; i < H; i++) {
        float acc = b1s[i];
        #pragma unroll
        for (int q = 0; q < H / 4; q++) {
            float4 w = W1s[i * (H / 4) + q];
            acc += w.x * a[4 * q + 0] + w.y * a[4 * q + 1]
                 + w.z * a[4 * q + 2] + w.w * a[4 * q + 3];
        }
        score += w2s[i] * fmaxf(acc, 0.f);
    }
    out[e] = score;
}

// ---------------- neighbor scatter: neigh[src] += h[dst] ----------------
// one thread per (edge, 4-float chunk); vector red cuts atomic instr count 4x
__global__ void k_scatter(const int* __restrict__ ei, int E_, int which) {
    const float* hin = which ? g_hB : g_hA;
    int idx = blockIdx.x * blockDim.x + threadIdx.x;
    if (idx >= E_ * 16) return;
    int e = idx >> 4, c = idx & 15;
    int s = ei[e];        // src row
    int d = ei[E_ + e];   // dst row
    float4 v = *(const float4*)(hin + ((size_t)d << 6) + (c << 2));
    float* p = g_neigh + ((size_t)s << 6) + (c << 2);
    asm volatile("red.global.add.v4.f32 [%0], {%1,%2,%3,%4};"
                 :: "l"(p), "f"(v.x), "f"(v.y), "f"(v.z), "f"(v.w)
                 : "memory");
}

// ---------------- SAGE combine: h = relu(Wself@h + bself + Wneigh@mean + bneigh) ----
// block = (64, 4): 4 nodes per block, thread tx = output feature.
// W matrices repacked in shared as W4[kg][j] (float4 over k) -> conflict-free LDS128.
__global__ void k_combine(const float* __restrict__ Wself, const float* __restrict__ bself,
                          const float* __restrict__ Wneigh, const float* __restrict__ bneigh,
                          float* hout, int which_in, int use_hout, int N_) {
    const float* hin = which_in ? g_hB : g_hA;
    __shared__ float4 WsA[16 * H];  // [kg][j]
    __shared__ float4 WnA[16 * H];
    __shared__ float4 hs4[4][16];
    __shared__ float4 ns4[4][16];
    int tx = threadIdx.x, ty = threadIdx.y;
    int t = ty * 64 + tx;
    const float4* gs = (const float4*)Wself;   // gs[j*16+kg] = W[j][4kg..4kg+3]
    const float4* gn = (const float4*)Wneigh;
    for (int i = t; i < H * 16; i += 256) {
        int j = i >> 4, kg = i & 15;
        WsA[kg * H + j] = gs[i];
        WnA[kg * H + j] = gn[i];
    }
    int n = blockIdx.x * 4 + ty;
    if (n < N_) {
        ((float*)hs4)[t] = hin[(size_t)n * H + tx];
        int c = g_cnt[n];
        float rd = (c > 0) ? 1.f / (float)c : 1.f;
        ((float*)ns4)[t] = g_neigh[(size_t)n * H + tx] * rd;
    }
    __syncthreads();
    if (n >= N_) return;
    float acc = bself[tx] + bneigh[tx];
    #pragma unroll
    for (int kg = 0; kg < 16; kg++) {
        float4 hv = hs4[ty][kg];
        float4 nv = ns4[ty][kg];
        float4 ws = WsA[kg * H + tx];
        float4 wn = WnA[kg * H + tx];
        acc += hv.x * ws.x + hv.y * ws.y + hv.z * ws.z + hv.w * ws.w
             + nv.x * wn.x + nv.y * wn.y + nv.z * wn.z + nv.w * wn.w;
    }
    float r = fmaxf(acc, 0.f);
    float* o = use_hout ? hout : g_hB;
    o[(size_t)n * H + tx] = r;
}

// ---------------- launch ----------------
extern "C" void kernel_launch(void* const* d_in, const int* in_sizes, int n_in,
                              void* d_out, int out_size) {
    const float* node_feats = (const float*)d_in[0];
    const float* edge_feats = (const float*)d_in[1];
    const float* enc        = (const float*)d_in[2];
    const int*   ei         = (const int*)d_in[3];
    const float* Wn     = (const float*)d_in[4];
    const float* bn     = (const float*)d_in[5];
    const float* We     = (const float*)d_in[6];
    const float* be     = (const float*)d_in[7];
    const float* Wself  = (const float*)d_in[8];   // (2,64,64)
    const float* bself  = (const float*)d_in[9];   // (2,64)
    const float* Wneigh = (const float*)d_in[10];
    const float* bneigh = (const float*)d_in[11];
    const float* Wa     = (const float*)d_in[12];
    const float* ba     = (const float*)d_in[13];
    const float* W1     = (const float*)d_in[14];
    const float* b1     = (const float*)d_in[15];
    const float* W2     = (const float*)d_in[16];
    const float* b2     = (const float*)d_in[17];

    int N_ = in_sizes[0] / 3;
    int E_ = in_sizes[1] / 3;
    float* out = (float*)d_out;
    float* h_out = out + E_;  // output = [scores (E), h (N*64)]

    int n64 = N_ * H;
    dim3 cdim(64, 4);

    // 1. zero degree + neighbor accumulator
    k_zero<<<(n64 + 255) / 256, 256>>>(n64, N_);
    // 2. fused edge constants
    k_pre<<<1, 64>>>(enc, Wa, ba, We, be);
    // 3. node_fc
    k_nodefc<<<(n64 + 255) / 256, 256>>>(node_feats, Wn, bn, N_);
    // 4. edge scorer (also counts degree) -> out[0:E]
    k_scorer<<<(E_ + 127) / 128, 128>>>(edge_feats, ei, W1, b1, W2, b2, out, E_);
    // 5. layer 0: scatter from hA, combine -> hB
    k_scatter<<<(E_ * 16 + 255) / 256, 256>>>(ei, E_, 0);
    k_combine<<<(N_ + 3) / 4, cdim>>>(Wself, bself, Wneigh, bneigh,
                                      nullptr, 0, 0, N_);
    // 6. re-zero neighbor accumulator
    k_zero<<<(n64 + 255) / 256, 256>>>(n64, 0);
    // 7. layer 1: scatter from hB, combine -> d_out h region
    k_scatter<<<(E_ * 16 + 255) / 256, 256>>>(ei, E_, 1);
    k_combine<<<(N_ + 3) / 4, cdim>>>(Wself + H * H, bself + H,
                                      Wneigh + H * H, bneigh + H,
                                      h_out, 1, 1, N_);
}

// round 8
// speedup vs baseline: 1.2670x; 1.2670x over previous
#include <cuda_runtime.h>

#define MAXN 50000
#define MAXE 1600000
#define H 64

typedef unsigned long long ull;

// ---------------- device scratch (no allocation allowed) ----------------
__device__ float g_hA[MAXN * H];     // node embeddings ping
__device__ float g_hB[MAXN * H];     // node embeddings pong
__device__ float g_neigh[MAXN * H];  // neighbor-sum accumulator
__device__ int   g_cnt[MAXN];        // out-degree (segment counts over src)
__device__ ull   g_ec2[4 * 32];      // fused edge consts, f32x2-packed: [comp][j2]

// ---------------- f32x2 helpers (packed fp32, sm_100+) ----------------
__device__ __forceinline__ ull pack2(float lo, float hi) {
    ull d; asm("mov.b64 %0, {%1,%2};" : "=l"(d) : "f"(lo), "f"(hi)); return d;
}
__device__ __forceinline__ void unpack2(ull v, float& lo, float& hi) {
    asm("mov.b64 {%0,%1}, %2;" : "=f"(lo), "=f"(hi) : "l"(v));
}
__device__ __forceinline__ ull fma2(ull a, ull b, ull c) {
    ull d; asm("fma.rn.f32x2 %0, %1, %2, %3;" : "=l"(d) : "l"(a), "l"(b), "l"(c));
    return d;
}
__device__ __forceinline__ float hadd2(ull v) {
    float lo, hi; unpack2(v, lo, hi); return lo + hi;
}

// ---------------- zero scratch ----------------
__global__ void k_zero(int n64, int n) {
    int i = blockIdx.x * blockDim.x + threadIdx.x;
    if (i < n64) g_neigh[i] = 0.f;
    if (i < n)   g_cnt[i] = 0;
}

// ---------------- precompute fused edge constants (packed) ----------------
// a = relu(M1 @ ef + c1), M1 = Wa[:,:64] @ We,
// c1 = Wa[:,:64] @ be + Wa[:,64:] @ vnf_mean + ba
__global__ void k_pre(const float* __restrict__ enc, const float* __restrict__ Wa,
                      const float* __restrict__ ba, const float* __restrict__ We,
                      const float* __restrict__ be) {
    __shared__ float vm[H];
    __shared__ float4 ecs[H];
    int j = threadIdx.x;  // 64 threads
    float s = 0.f;
    #pragma unroll
    for (int v = 0; v < 16; v++) s += enc[v * H + j];
    vm[j] = s * (1.f / 16.f);
    __syncthreads();
    const float* wr = Wa + j * 128;
    float m0 = 0.f, m1 = 0.f, m2 = 0.f, c = ba[j];
    #pragma unroll 8
    for (int m = 0; m < H; m++) {
        float w = wr[m];
        m0 += w * We[m * 3 + 0];
        m1 += w * We[m * 3 + 1];
        m2 += w * We[m * 3 + 2];
        c  += w * be[m];
    }
    #pragma unroll 8
    for (int d = 0; d < H; d++) c += wr[H + d] * vm[d];
    ecs[j] = make_float4(m0, m1, m2, c);
    __syncthreads();
    if (j < 32) {
        float4 lo = ecs[2 * j], hi = ecs[2 * j + 1];
        g_ec2[0 * 32 + j] = pack2(lo.x, hi.x);
        g_ec2[1 * 32 + j] = pack2(lo.y, hi.y);
        g_ec2[2 * 32 + j] = pack2(lo.z, hi.z);
        g_ec2[3 * 32 + j] = pack2(lo.w, hi.w);
    }
}

// ---------------- node_fc: h = node_feats @ Wn.T + bn ----------------
__global__ void k_nodefc(const float* __restrict__ nf, const float* __restrict__ Wn,
                         const float* __restrict__ bn, int N_) {
    __shared__ float Ws[H * 3];
    __shared__ float bs[H];
    int t = threadIdx.x;
    if (t < H * 3) Ws[t] = Wn[t];
    if (t < H) bs[t] = bn[t];
    __syncthreads();
    int idx = blockIdx.x * blockDim.x + t;
    if (idx >= N_ * H) return;
    int n = idx >> 6, j = idx & 63;
    float f0 = nf[n * 3 + 0], f1 = nf[n * 3 + 1], f2 = nf[n * 3 + 2];
    g_hA[idx] = Ws[j * 3 + 0] * f0 + Ws[j * 3 + 1] * f1 + Ws[j * 3 + 2] * f2 + bs[j];
}

// ---------------- fused edge scorer + degree count (f32x2) ----------------
// score = b2 + w2 . relu(W1 @ relu(M1 @ ef + c1) + b1)
__global__ __launch_bounds__(128) void k_scorer(
    const float* __restrict__ ef, const int* __restrict__ src,
    const float* __restrict__ W1, const float* __restrict__ b1,
    const float* __restrict__ W2, const float* __restrict__ b2,
    float* __restrict__ out, int E_) {
    __shared__ __align__(16) ull W1p[H * 32];   // 16 KB: [i][q2] packed pairs
    __shared__ ull ec2s[4 * 32];
    __shared__ float b1s[H], w2sv[H];
    __shared__ float b2s;
    int t = threadIdx.x;
    {   // copy W1 (row-major floats) as packed pairs; pairing matches a2 layout
        const ulonglong2* Wg = (const ulonglong2*)W1;
        ulonglong2* Wp = (ulonglong2*)W1p;
        for (int i = t; i < H * 16; i += 128) Wp[i] = Wg[i];
    }
    ec2s[t] = g_ec2[t];          // t in [0,128) covers all 128 entries
    if (t < H) { b1s[t] = b1[t]; w2sv[t] = W2[t]; }
    if (t == 0) b2s = b2[0];
    __syncthreads();

    int e = blockIdx.x * 128 + t;
    if (e >= E_) return;

    atomicAdd(&g_cnt[src[e]], 1);   // degree (segment count over src)

    float f0 = ef[e * 3 + 0], f1 = ef[e * 3 + 1], f2 = ef[e * 3 + 2];
    ull f0p = pack2(f0, f0), f1p = pack2(f1, f1), f2p = pack2(f2, f2);

    ull a2[32];
    #pragma unroll
    for (int q = 0; q < 32; q++) {
        ull v = fma2(ec2s[64 + q], f2p, ec2s[96 + q]);
        v = fma2(ec2s[32 + q], f1p, v);
        v = fma2(ec2s[q],      f0p, v);
        float lo, hi; unpack2(v, lo, hi);
        a2[q] = pack2(fmaxf(lo, 0.f), fmaxf(hi, 0.f));
    }

    float score = b2s;
    #pragma unroll 2
    for (int i = 0; i < H; i++) {
        const ulonglong2* row = (const ulonglong2*)(W1p + i * 32);
        ull accA = 0ull, accB = 0ull;   // 0 bits == {0.f, 0.f}
        #pragma unroll
        for (int q = 0; q < 16; q++) {
            ulonglong2 w = row[q];
            accA = fma2(w.x, a2[2 * q + 0], accA);
            accB = fma2(w.y, a2[2 * q + 1], accB);
        }
        float sum = hadd2(accA) + hadd2(accB) + b1s[i];
        score = fmaf(w2sv[i], fmaxf(sum, 0.f), score);
    }
    out[e] = score;
}

// ---------------- neighbor scatter: neigh[src] += h[dst] ----------------
__global__ void k_scatter(const int* __restrict__ ei, int E_, int which) {
    const float* hin = which ? g_hB : g_hA;
    int idx = blockIdx.x * blockDim.x + threadIdx.x;
    if (idx >= E_ * 16) return;
    int e = idx >> 4, c = idx & 15;
    int s = ei[e];        // src row
    int d = ei[E_ + e];   // dst row
    float4 v = *(const float4*)(hin + ((size_t)d << 6) + (c << 2));
    float* p = g_neigh + ((size_t)s << 6) + (c << 2);
    asm volatile("red.global.add.v4.f32 [%0], {%1,%2,%3,%4};"
                 :: "l"(p), "f"(v.x), "f"(v.y), "f"(v.z), "f"(v.w)
                 : "memory");
}

// ---------------- SAGE combine (persistent): h = relu(Wself@h + Wneigh@mean + b) --
// block = (64,4); grid-stride over 4-node tiles; W loaded to shared ONCE per block.
__global__ void k_combine(const float* __restrict__ Wself, const float* __restrict__ bself,
                          const float* __restrict__ Wneigh, const float* __restrict__ bneigh,
                          float* hout, int which_in, int use_hout, int N_) {
    const float* hin = which_in ? g_hB : g_hA;
    __shared__ float4 WsA[16 * H];  // [kg][j]
    __shared__ float4 WnA[16 * H];
    __shared__ float4 hs4[4][16];
    __shared__ float4 ns4[4][16];
    int tx = threadIdx.x, ty = threadIdx.y;
    int t = ty * 64 + tx;
    const float4* gs = (const float4*)Wself;
    const float4* gn = (const float4*)Wneigh;
    for (int i = t; i < H * 16; i += 256) {
        int j = i >> 4, kg = i & 15;
        WsA[kg * H + j] = gs[i];
        WnA[kg * H + j] = gn[i];
    }
    float bias = bself[tx] + bneigh[tx];
    float* o = use_hout ? hout : g_hB;
    int ntiles = (N_ + 3) / 4;
    for (int tile = blockIdx.x; tile < ntiles; tile += gridDim.x) {
        __syncthreads();   // also covers the one-time W load on iter 0
        int n = tile * 4 + ty;
        if (n < N_) {
            ((float*)hs4)[t] = hin[(size_t)n * H + tx];
            int c = g_cnt[n];
            float rd = (c > 0) ? 1.f / (float)c : 1.f;
            ((float*)ns4)[t] = g_neigh[(size_t)n * H + tx] * rd;
        }
        __syncthreads();
        if (n < N_) {
            float acc = bias;
            #pragma unroll
            for (int kg = 0; kg < 16; kg++) {
                float4 hv = hs4[ty][kg];
                float4 nv = ns4[ty][kg];
                float4 ws = WsA[kg * H + tx];
                float4 wn = WnA[kg * H + tx];
                acc += hv.x * ws.x + hv.y * ws.y + hv.z * ws.z + hv.w * ws.w
                     + nv.x * wn.x + nv.y * wn.y + nv.z * wn.z + nv.w * wn.w;
            }
            o[(size_t)n * H + tx] = fmaxf(acc, 0.f);
        }
    }
}

// ---------------- launch ----------------
extern "C" void kernel_launch(void* const* d_in, const int* in_sizes, int n_in,
                              void* d_out, int out_size) {
    const float* node_feats = (const float*)d_in[0];
    const float* edge_feats = (const float*)d_in[1];
    const float* enc        = (const float*)d_in[2];
    const int*   ei         = (const int*)d_in[3];
    const float* Wn     = (const float*)d_in[4];
    const float* bn     = (const float*)d_in[5];
    const float* We     = (const float*)d_in[6];
    const float* be     = (const float*)d_in[7];
    const float* Wself  = (const float*)d_in[8];   // (2,64,64)
    const float* bself  = (const float*)d_in[9];   // (2,64)
    const float* Wneigh = (const float*)d_in[10];
    const float* bneigh = (const float*)d_in[11];
    const float* Wa     = (const float*)d_in[12];
    const float* ba     = (const float*)d_in[13];
    const float* W1     = (const float*)d_in[14];
    const float* b1     = (const float*)d_in[15];
    const float* W2     = (const float*)d_in[16];
    const float* b2     = (const float*)d_in[17];

    int N_ = in_sizes[0] / 3;
    int E_ = in_sizes[1] / 3;
    float* out = (float*)d_out;
    float* h_out = out + E_;  // output = [scores (E), h (N*64)]

    int n64 = N_ * H;
    dim3 cdim(64, 4);
    int cgrid = 888;  // ~6 blocks/SM (34KB smem each)

    // 1. zero degree + neighbor accumulator
    k_zero<<<(n64 + 255) / 256, 256>>>(n64, N_);
    // 2. fused edge constants (packed f32x2 layout)
    k_pre<<<1, 64>>>(enc, Wa, ba, We, be);
    // 3. node_fc
    k_nodefc<<<(n64 + 255) / 256, 256>>>(node_feats, Wn, bn, N_);
    // 4. edge scorer (also counts degree) -> out[0:E]
    k_scorer<<<(E_ + 127) / 128, 128>>>(edge_feats, ei, W1, b1, W2, b2, out, E_);
    // 5. layer 0: scatter from hA, combine -> hB
    k_scatter<<<(E_ * 16 + 255) / 256, 256>>>(ei, E_, 0);
    k_combine<<<cgrid, cdim>>>(Wself, bself, Wneigh, bneigh, nullptr, 0, 0, N_);
    // 6. re-zero neighbor accumulator
    k_zero<<<(n64 + 255) / 256, 256>>>(n64, 0);
    // 7. layer 1: scatter from hB, combine -> d_out h region
    k_scatter<<<(E_ * 16 + 255) / 256, 256>>>(ei, E_, 1);
    k_combine<<<cgrid, cdim>>>(Wself + H * H, bself + H,
                               Wneigh + H * H, bneigh + H,
                               h_out, 1, 1, N_);
}

// round 9
// speedup vs baseline: 1.5060x; 1.1887x over previous
#include <cuda_runtime.h>

#define MAXN 50000
#define MAXE 1600000
#define H 64

typedef unsigned long long ull;

// ---------------- device scratch (no allocation allowed) ----------------
__device__ float g_hA[MAXN * H];     // node embeddings ping
__device__ float g_hB[MAXN * H];     // node embeddings pong
__device__ float g_neigh[MAXN * H];  // neighbor-sum accumulator
__device__ int   g_cnt[MAXN];        // out-degree (segment counts over src)
__device__ ull   g_ec2[4 * 32];      // fused edge consts, f32x2-packed: [comp][j2]

// ---------------- f32x2 helpers (packed fp32, sm_100+) ----------------
__device__ __forceinline__ ull pack2(float lo, float hi) {
    ull d; asm("mov.b64 %0, {%1,%2};" : "=l"(d) : "f"(lo), "f"(hi)); return d;
}
__device__ __forceinline__ void unpack2(ull v, float& lo, float& hi) {
    asm("mov.b64 {%0,%1}, %2;" : "=f"(lo), "=f"(hi) : "l"(v));
}
__device__ __forceinline__ ull fma2(ull a, ull b, ull c) {
    ull d; asm("fma.rn.f32x2 %0, %1, %2, %3;" : "=l"(d) : "l"(a), "l"(b), "l"(c));
    return d;
}
__device__ __forceinline__ float hadd2(ull v) {
    float lo, hi; unpack2(v, lo, hi); return lo + hi;
}

// ---------------- zero scratch ----------------
__global__ void k_zero(int n64, int n) {
    int i = blockIdx.x * blockDim.x + threadIdx.x;
    if (i < n64) g_neigh[i] = 0.f;
    if (i < n)   g_cnt[i] = 0;
}

// ---------------- precompute fused edge constants (packed) ----------------
// a = relu(M1 @ ef + c1), M1 = Wa[:,:64] @ We,
// c1 = Wa[:,:64] @ be + Wa[:,64:] @ vnf_mean + ba
__global__ void k_pre(const float* __restrict__ enc, const float* __restrict__ Wa,
                      const float* __restrict__ ba, const float* __restrict__ We,
                      const float* __restrict__ be) {
    __shared__ float vm[H];
    __shared__ float4 ecs[H];
    int j = threadIdx.x;  // 64 threads
    float s = 0.f;
    #pragma unroll
    for (int v = 0; v < 16; v++) s += enc[v * H + j];
    vm[j] = s * (1.f / 16.f);
    __syncthreads();
    const float* wr = Wa + j * 128;
    float m0 = 0.f, m1 = 0.f, m2 = 0.f, c = ba[j];
    #pragma unroll 8
    for (int m = 0; m < H; m++) {
        float w = wr[m];
        m0 += w * We[m * 3 + 0];
        m1 += w * We[m * 3 + 1];
        m2 += w * We[m * 3 + 2];
        c  += w * be[m];
    }
    #pragma unroll 8
    for (int d = 0; d < H; d++) c += wr[H + d] * vm[d];
    ecs[j] = make_float4(m0, m1, m2, c);
    __syncthreads();
    if (j < 32) {
        float4 lo = ecs[2 * j], hi = ecs[2 * j + 1];
        g_ec2[0 * 32 + j] = pack2(lo.x, hi.x);
        g_ec2[1 * 32 + j] = pack2(lo.y, hi.y);
        g_ec2[2 * 32 + j] = pack2(lo.z, hi.z);
        g_ec2[3 * 32 + j] = pack2(lo.w, hi.w);
    }
}

// ---------------- node_fc: h = node_feats @ Wn.T + bn ----------------
__global__ void k_nodefc(const float* __restrict__ nf, const float* __restrict__ Wn,
                         const float* __restrict__ bn, int N_) {
    __shared__ float Ws[H * 3];
    __shared__ float bs[H];
    int t = threadIdx.x;
    if (t < H * 3) Ws[t] = Wn[t];
    if (t < H) bs[t] = bn[t];
    __syncthreads();
    int idx = blockIdx.x * blockDim.x + t;
    if (idx >= N_ * H) return;
    int n = idx >> 6, j = idx & 63;
    float f0 = nf[n * 3 + 0], f1 = nf[n * 3 + 1], f2 = nf[n * 3 + 2];
    g_hA[idx] = Ws[j * 3 + 0] * f0 + Ws[j * 3 + 1] * f1 + Ws[j * 3 + 2] * f2 + bs[j];
}

// ---------------- fused edge scorer + degree count (f32x2, 2 edges/thread) ----
// score = b2 + w2 . relu(W1 @ relu(M1 @ ef + c1) + b1)
// Each thread scores edges (base+t) and (base+t+128); each W1 shared load
// feeds 4 fma2 -> LDS.128 per edge halves vs 1 edge/thread.
__global__ __launch_bounds__(128) void k_scorer(
    const float* __restrict__ ef, const int* __restrict__ src,
    const float* __restrict__ W1, const float* __restrict__ b1,
    const float* __restrict__ W2, const float* __restrict__ b2,
    float* __restrict__ out, int E_) {
    __shared__ __align__(16) ull W1p[H * 32];   // 16 KB: [i][q2] packed pairs
    __shared__ ull ec2s[4 * 32];
    __shared__ float b1s[H], w2sv[H];
    __shared__ float b2s;
    int t = threadIdx.x;
    {   // copy W1 (row-major floats) as packed pairs; pairing matches a2 layout
        const ulonglong2* Wg = (const ulonglong2*)W1;
        ulonglong2* Wp = (ulonglong2*)W1p;
        for (int i = t; i < H * 16; i += 128) Wp[i] = Wg[i];
    }
    ec2s[t] = g_ec2[t];          // t in [0,128) covers all 128 entries
    if (t < H) { b1s[t] = b1[t]; w2sv[t] = W2[t]; }
    if (t == 0) b2s = b2[0];
    __syncthreads();

    int base = blockIdx.x * 256;
    int e0 = base + t;
    if (e0 >= E_) return;
    int e1 = e0 + 128;
    bool v1 = (e1 < E_);
    int eL = v1 ? e1 : e0;       // safe address for the second edge's loads

    atomicAdd(&g_cnt[src[e0]], 1);            // degree (segment count over src)
    if (v1) atomicAdd(&g_cnt[src[e1]], 1);

    float f00 = ef[e0 * 3 + 0], f01 = ef[e0 * 3 + 1], f02 = ef[e0 * 3 + 2];
    float f10 = ef[eL * 3 + 0], f11 = ef[eL * 3 + 1], f12 = ef[eL * 3 + 2];
    ull f00p = pack2(f00, f00), f01p = pack2(f01, f01), f02p = pack2(f02, f02);
    ull f10p = pack2(f10, f10), f11p = pack2(f11, f11), f12p = pack2(f12, f12);

    ull a0[32], a1[32];
    #pragma unroll
    for (int q = 0; q < 32; q++) {
        ull c1v = ec2s[96 + q], m0 = ec2s[q], m1 = ec2s[32 + q], m2 = ec2s[64 + q];
        ull v = fma2(m2, f02p, c1v);
        v = fma2(m1, f01p, v);
        v = fma2(m0, f00p, v);
        float lo, hi; unpack2(v, lo, hi);
        a0[q] = pack2(fmaxf(lo, 0.f), fmaxf(hi, 0.f));
        ull u = fma2(m2, f12p, c1v);
        u = fma2(m1, f11p, u);
        u = fma2(m0, f10p, u);
        unpack2(u, lo, hi);
        a1[q] = pack2(fmaxf(lo, 0.f), fmaxf(hi, 0.f));
    }

    float score0 = b2s, score1 = b2s;
    #pragma unroll 2
    for (int i = 0; i < H; i++) {
        const ulonglong2* row = (const ulonglong2*)(W1p + i * 32);
        ull aA0 = 0ull, aB0 = 0ull, aA1 = 0ull, aB1 = 0ull;  // 0 bits == {0,0}
        #pragma unroll
        for (int q = 0; q < 16; q++) {
            ulonglong2 w = row[q];      // one LDS.128 serves both edges
            aA0 = fma2(w.x, a0[2 * q + 0], aA0);
            aB0 = fma2(w.y, a0[2 * q + 1], aB0);
            aA1 = fma2(w.x, a1[2 * q + 0], aA1);
            aB1 = fma2(w.y, a1[2 * q + 1], aB1);
        }
        float s0 = hadd2(aA0) + hadd2(aB0) + b1s[i];
        float s1 = hadd2(aA1) + hadd2(aB1) + b1s[i];
        score0 = fmaf(w2sv[i], fmaxf(s0, 0.f), score0);
        score1 = fmaf(w2sv[i], fmaxf(s1, 0.f), score1);
    }
    out[e0] = score0;
    if (v1) out[e1] = score1;
}

// ---------------- neighbor scatter: neigh[src] += h[dst] ----------------
__global__ void k_scatter(const int* __restrict__ ei, int E_, int which) {
    const float* hin = which ? g_hB : g_hA;
    int idx = blockIdx.x * blockDim.x + threadIdx.x;
    if (idx >= E_ * 16) return;
    int e = idx >> 4, c = idx & 15;
    int s = ei[e];        // src row
    int d = ei[E_ + e];   // dst row
    float4 v = *(const float4*)(hin + ((size_t)d << 6) + (c << 2));
    float* p = g_neigh + ((size_t)s << 6) + (c << 2);
    asm volatile("red.global.add.v4.f32 [%0], {%1,%2,%3,%4};"
                 :: "l"(p), "f"(v.x), "f"(v.y), "f"(v.z), "f"(v.w)
                 : "memory");
}

// ---------------- SAGE combine (persistent): h = relu(Wself@h + Wneigh@mean + b) --
// block = (64,4); grid-stride over 4-node tiles; W loaded to shared ONCE per block.
__global__ void k_combine(const float* __restrict__ Wself, const float* __restrict__ bself,
                          const float* __restrict__ Wneigh, const float* __restrict__ bneigh,
                          float* hout, int which_in, int use_hout, int N_) {
    const float* hin = which_in ? g_hB : g_hA;
    __shared__ float4 WsA[16 * H];  // [kg][j]
    __shared__ float4 WnA[16 * H];
    __shared__ float4 hs4[4][16];
    __shared__ float4 ns4[4][16];
    int tx = threadIdx.x, ty = threadIdx.y;
    int t = ty * 64 + tx;
    const float4* gs = (const float4*)Wself;
    const float4* gn = (const float4*)Wneigh;
    for (int i = t; i < H * 16; i += 256) {
        int j = i >> 4, kg = i & 15;
        WsA[kg * H + j] = gs[i];
        WnA[kg * H + j] = gn[i];
    }
    float bias = bself[tx] + bneigh[tx];
    float* o = use_hout ? hout : g_hB;
    int ntiles = (N_ + 3) / 4;
    for (int tile = blockIdx.x; tile < ntiles; tile += gridDim.x) {
        __syncthreads();   // also covers the one-time W load on iter 0
        int n = tile * 4 + ty;
        if (n < N_) {
            ((float*)hs4)[t] = hin[(size_t)n * H + tx];
            int c = g_cnt[n];
            float rd = (c > 0) ? 1.f / (float)c : 1.f;
            ((float*)ns4)[t] = g_neigh[(size_t)n * H + tx] * rd;
        }
        __syncthreads();
        if (n < N_) {
            float acc = bias;
            #pragma unroll
            for (int kg = 0; kg < 16; kg++) {
                float4 hv = hs4[ty][kg];
                float4 nv = ns4[ty][kg];
                float4 ws = WsA[kg * H + tx];
                float4 wn = WnA[kg * H + tx];
                acc += hv.x * ws.x + hv.y * ws.y + hv.z * ws.z + hv.w * ws.w
                     + nv.x * wn.x + nv.y * wn.y + nv.z * wn.z + nv.w * wn.w;
            }
            o[(size_t)n * H + tx] = fmaxf(acc, 0.f);
        }
    }
}

// ---------------- launch ----------------
extern "C" void kernel_launch(void* const* d_in, const int* in_sizes, int n_in,
                              void* d_out, int out_size) {
    const float* node_feats = (const float*)d_in[0];
    const float* edge_feats = (const float*)d_in[1];
    const float* enc        = (const float*)d_in[2];
    const int*   ei         = (const int*)d_in[3];
    const float* Wn     = (const float*)d_in[4];
    const float* bn     = (const float*)d_in[5];
    const float* We     = (const float*)d_in[6];
    const float* be     = (const float*)d_in[7];
    const float* Wself  = (const float*)d_in[8];   // (2,64,64)
    const float* bself  = (const float*)d_in[9];   // (2,64)
    const float* Wneigh = (const float*)d_in[10];
    const float* bneigh = (const float*)d_in[11];
    const float* Wa     = (const float*)d_in[12];
    const float* ba     = (const float*)d_in[13];
    const float* W1     = (const float*)d_in[14];
    const float* b1     = (const float*)d_in[15];
    const float* W2     = (const float*)d_in[16];
    const float* b2     = (const float*)d_in[17];

    int N_ = in_sizes[0] / 3;
    int E_ = in_sizes[1] / 3;
    float* out = (float*)d_out;
    float* h_out = out + E_;  // output = [scores (E), h (N*64)]

    int n64 = N_ * H;
    dim3 cdim(64, 4);
    int cgrid = 888;  // persistent combine blocks

    // 1. zero degree + neighbor accumulator
    k_zero<<<(n64 + 255) / 256, 256>>>(n64, N_);
    // 2. fused edge constants (packed f32x2 layout)
    k_pre<<<1, 64>>>(enc, Wa, ba, We, be);
    // 3. node_fc
    k_nodefc<<<(n64 + 255) / 256, 256>>>(node_feats, Wn, bn, N_);
    // 4. edge scorer (also counts degree), 2 edges/thread -> out[0:E]
    k_scorer<<<(E_ + 255) / 256, 128>>>(edge_feats, ei, W1, b1, W2, b2, out, E_);
    // 5. layer 0: scatter from hA, combine -> hB
    k_scatter<<<(E_ * 16 + 255) / 256, 256>>>(ei, E_, 0);
    k_combine<<<cgrid, cdim>>>(Wself, bself, Wneigh, bneigh, nullptr, 0, 0, N_);
    // 6. re-zero neighbor accumulator
    k_zero<<<(n64 + 255) / 256, 256>>>(n64, 0);
    // 7. layer 1: scatter from hB, combine -> d_out h region
    k_scatter<<<(E_ * 16 + 255) / 256, 256>>>(ei, E_, 1);
    k_combine<<<cgrid, cdim>>>(Wself + H * H, bself + H,
                               Wneigh + H * H, bneigh + H,
                               h_out, 1, 1, N_);
}

// round 10
// speedup vs baseline: 1.6767x; 1.1133x over previous
#include <cuda_runtime.h>

#define MAXN 50000
#define MAXE 1600000
#define H 64

typedef unsigned long long ull;

// ---------------- device scratch (no allocation allowed) ----------------
__device__ float g_hA[MAXN * H];     // node embeddings ping
__device__ float g_hB[MAXN * H];     // node embeddings pong
__device__ float g_neigh[MAXN * H];  // neighbor MEAN per node
__device__ int   g_cnt[MAXN];        // out-degree (segment counts over src)
__device__ int   g_off[MAXN];        // CSR row offsets (exclusive scan of cnt)
__device__ int   g_cur[MAXN];        // fill cursors
__device__ int   g_adj[MAXE];        // CSR adjacency: dst lists grouped by src
__device__ ull   g_ec2[4 * 32];      // fused edge consts, f32x2-packed

// ---------------- f32x2 helpers (packed fp32, sm_100+) ----------------
__device__ __forceinline__ ull pack2(float lo, float hi) {
    ull d; asm("mov.b64 %0, {%1,%2};" : "=l"(d) : "f"(lo), "f"(hi)); return d;
}
__device__ __forceinline__ void unpack2(ull v, float& lo, float& hi) {
    asm("mov.b64 {%0,%1}, %2;" : "=f"(lo), "=f"(hi) : "l"(v));
}
__device__ __forceinline__ ull fma2(ull a, ull b, ull c) {
    ull d; asm("fma.rn.f32x2 %0, %1, %2, %3;" : "=l"(d) : "l"(a), "l"(b), "l"(c));
    return d;
}
__device__ __forceinline__ float hadd2(ull v) {
    float lo, hi; unpack2(v, lo, hi); return lo + hi;
}

// ---------------- zero degree counters ----------------
__global__ void k_zero_cnt(int n) {
    int i = blockIdx.x * blockDim.x + threadIdx.x;
    if (i < n) g_cnt[i] = 0;
}

// ---------------- precompute fused edge constants (packed) ----------------
__global__ void k_pre(const float* __restrict__ enc, const float* __restrict__ Wa,
                      const float* __restrict__ ba, const float* __restrict__ We,
                      const float* __restrict__ be) {
    __shared__ float vm[H];
    __shared__ float4 ecs[H];
    int j = threadIdx.x;  // 64 threads
    float s = 0.f;
    #pragma unroll
    for (int v = 0; v < 16; v++) s += enc[v * H + j];
    vm[j] = s * (1.f / 16.f);
    __syncthreads();
    const float* wr = Wa + j * 128;
    float m0 = 0.f, m1 = 0.f, m2 = 0.f, c = ba[j];
    #pragma unroll 8
    for (int m = 0; m < H; m++) {
        float w = wr[m];
        m0 += w * We[m * 3 + 0];
        m1 += w * We[m * 3 + 1];
        m2 += w * We[m * 3 + 2];
        c  += w * be[m];
    }
    #pragma unroll 8
    for (int d = 0; d < H; d++) c += wr[H + d] * vm[d];
    ecs[j] = make_float4(m0, m1, m2, c);
    __syncthreads();
    if (j < 32) {
        float4 lo = ecs[2 * j], hi = ecs[2 * j + 1];
        g_ec2[0 * 32 + j] = pack2(lo.x, hi.x);
        g_ec2[1 * 32 + j] = pack2(lo.y, hi.y);
        g_ec2[2 * 32 + j] = pack2(lo.z, hi.z);
        g_ec2[3 * 32 + j] = pack2(lo.w, hi.w);
    }
}

// ---------------- node_fc: h = node_feats @ Wn.T + bn ----------------
__global__ void k_nodefc(const float* __restrict__ nf, const float* __restrict__ Wn,
                         const float* __restrict__ bn, int N_) {
    __shared__ float Ws[H * 3];
    __shared__ float bs[H];
    int t = threadIdx.x;
    if (t < H * 3) Ws[t] = Wn[t];
    if (t < H) bs[t] = bn[t];
    __syncthreads();
    int idx = blockIdx.x * blockDim.x + t;
    if (idx >= N_ * H) return;
    int n = idx >> 6, j = idx & 63;
    float f0 = nf[n * 3 + 0], f1 = nf[n * 3 + 1], f2 = nf[n * 3 + 2];
    g_hA[idx] = Ws[j * 3 + 0] * f0 + Ws[j * 3 + 1] * f1 + Ws[j * 3 + 2] * f2 + bs[j];
}

// ---------------- fused edge scorer + degree count (f32x2, 2 edges/thread) ----
__global__ __launch_bounds__(128) void k_scorer(
    const float* __restrict__ ef, const int* __restrict__ src,
    const float* __restrict__ W1, const float* __restrict__ b1,
    const float* __restrict__ W2, const float* __restrict__ b2,
    float* __restrict__ out, int E_) {
    __shared__ __align__(16) ull W1p[H * 32];   // 16 KB: [i][q2] packed pairs
    __shared__ ull ec2s[4 * 32];
    __shared__ float b1s[H], w2sv[H];
    __shared__ float b2s;
    int t = threadIdx.x;
    {
        const ulonglong2* Wg = (const ulonglong2*)W1;
        ulonglong2* Wp = (ulonglong2*)W1p;
        for (int i = t; i < H * 16; i += 128) Wp[i] = Wg[i];
    }
    ec2s[t] = g_ec2[t];
    if (t < H) { b1s[t] = b1[t]; w2sv[t] = W2[t]; }
    if (t == 0) b2s = b2[0];
    __syncthreads();

    int base = blockIdx.x * 256;
    int e0 = base + t;
    if (e0 >= E_) return;
    int e1 = e0 + 128;
    bool v1 = (e1 < E_);
    int eL = v1 ? e1 : e0;

    atomicAdd(&g_cnt[src[e0]], 1);
    if (v1) atomicAdd(&g_cnt[src[e1]], 1);

    float f00 = ef[e0 * 3 + 0], f01 = ef[e0 * 3 + 1], f02 = ef[e0 * 3 + 2];
    float f10 = ef[eL * 3 + 0], f11 = ef[eL * 3 + 1], f12 = ef[eL * 3 + 2];
    ull f00p = pack2(f00, f00), f01p = pack2(f01, f01), f02p = pack2(f02, f02);
    ull f10p = pack2(f10, f10), f11p = pack2(f11, f11), f12p = pack2(f12, f12);

    ull a0[32], a1[32];
    #pragma unroll
    for (int q = 0; q < 32; q++) {
        ull c1v = ec2s[96 + q], m0 = ec2s[q], m1 = ec2s[32 + q], m2 = ec2s[64 + q];
        ull v = fma2(m2, f02p, c1v);
        v = fma2(m1, f01p, v);
        v = fma2(m0, f00p, v);
        float lo, hi; unpack2(v, lo, hi);
        a0[q] = pack2(fmaxf(lo, 0.f), fmaxf(hi, 0.f));
        ull u = fma2(m2, f12p, c1v);
        u = fma2(m1, f11p, u);
        u = fma2(m0, f10p, u);
        unpack2(u, lo, hi);
        a1[q] = pack2(fmaxf(lo, 0.f), fmaxf(hi, 0.f));
    }

    float score0 = b2s, score1 = b2s;
    #pragma unroll 2
    for (int i = 0; i < H; i++) {
        const ulonglong2* row = (const ulonglong2*)(W1p + i * 32);
        ull aA0 = 0ull, aB0 = 0ull, aA1 = 0ull, aB1 = 0ull;
        #pragma unroll
        for (int q = 0; q < 16; q++) {
            ulonglong2 w = row[q];      // one LDS.128 serves both edges
            aA0 = fma2(w.x, a0[2 * q + 0], aA0);
            aB0 = fma2(w.y, a0[2 * q + 1], aB0);
            aA1 = fma2(w.x, a1[2 * q + 0], aA1);
            aB1 = fma2(w.y, a1[2 * q + 1], aB1);
        }
        float s0 = hadd2(aA0) + hadd2(aB0) + b1s[i];
        float s1 = hadd2(aA1) + hadd2(aB1) + b1s[i];
        score0 = fmaf(w2sv[i], fmaxf(s0, 0.f), score0);
        score1 = fmaf(w2sv[i], fmaxf(s1, 0.f), score1);
    }
    out[e0] = score0;
    if (v1) out[e1] = score1;
}

// ---------------- exclusive scan of g_cnt -> g_off, g_cur (single block) ------
__global__ __launch_bounds__(1024) void k_scan(int N_) {
    __shared__ int warpsum[32];
    __shared__ int warpoff[32];
    __shared__ int carry_s;
    int t = threadIdx.x, lane = t & 31, wid = t >> 5;
    if (t == 0) carry_s = 0;
    __syncthreads();
    for (int base = 0; base < N_; base += 1024) {
        int i = base + t;
        int v = (i < N_) ? g_cnt[i] : 0;
        // warp inclusive scan
        int incl = v;
        #pragma unroll
        for (int off = 1; off < 32; off <<= 1) {
            int x = __shfl_up_sync(0xffffffffu, incl, off);
            if (lane >= off) incl += x;
        }
        if (lane == 31) warpsum[wid] = incl;
        __syncthreads();
        if (wid == 0) {
            int s = warpsum[lane];
            int si = s;
            #pragma unroll
            for (int off = 1; off < 32; off <<= 1) {
                int x = __shfl_up_sync(0xffffffffu, si, off);
                if (lane >= off) si += x;
            }
            warpoff[lane] = si - s;   // exclusive over warps
        }
        __syncthreads();
        int excl = incl - v + warpoff[wid] + carry_s;
        if (i < N_) { g_off[i] = excl; g_cur[i] = excl; }
        __syncthreads();   // everyone has read carry_s / warpoff
        if (t == 0) carry_s += warpoff[31] + warpsum[31];
        __syncthreads();
    }
}

// ---------------- CSR fill: adj grouped by src ----------------
__global__ void k_fill(const int* __restrict__ ei, int E_) {
    int e = blockIdx.x * blockDim.x + threadIdx.x;
    if (e >= E_) return;
    int s = ei[e], d = ei[E_ + e];
    int pos = atomicAdd(&g_cur[s], 1);
    g_adj[pos] = d;
}

// ---------------- gather aggregation: neigh_mean per node (warp/node) --------
__global__ void k_agg(int which, int N_) {
    const float2* hin2 = (const float2*)(which ? g_hB : g_hA);
    int w = (blockIdx.x * blockDim.x + threadIdx.x) >> 5;
    int lane = threadIdx.x & 31;
    if (w >= N_) return;
    int beg = g_off[w], cnt = g_cnt[w];
    int end = beg + cnt;
    float ax = 0.f, ay = 0.f, bx = 0.f, by = 0.f;
    int i = beg;
    for (; i + 1 < end; i += 2) {
        int d0 = g_adj[i], d1 = g_adj[i + 1];
        float2 v0 = hin2[d0 * 32 + lane];
        float2 v1 = hin2[d1 * 32 + lane];
        ax += v0.x; ay += v0.y;
        bx += v1.x; by += v1.y;
    }
    if (i < end) {
        int d = g_adj[i];
        float2 v = hin2[d * 32 + lane];
        ax += v.x; ay += v.y;
    }
    float rd = (cnt > 0) ? 1.f / (float)cnt : 0.f;
    float2 o; o.x = (ax + bx) * rd; o.y = (ay + by) * rd;
    ((float2*)g_neigh)[w * 32 + lane] = o;
}

// ---------------- SAGE combine (persistent): h = relu(Wself@h + Wneigh@mean + b)
__global__ void k_combine(const float* __restrict__ Wself, const float* __restrict__ bself,
                          const float* __restrict__ Wneigh, const float* __restrict__ bneigh,
                          float* hout, int which_in, int use_hout, int N_) {
    const float* hin = which_in ? g_hB : g_hA;
    __shared__ float4 WsA[16 * H];  // [kg][j]
    __shared__ float4 WnA[16 * H];
    __shared__ float4 hs4[4][16];
    __shared__ float4 ns4[4][16];
    int tx = threadIdx.x, ty = threadIdx.y;
    int t = ty * 64 + tx;
    const float4* gs = (const float4*)Wself;
    const float4* gn = (const float4*)Wneigh;
    for (int i = t; i < H * 16; i += 256) {
        int j = i >> 4, kg = i & 15;
        WsA[kg * H + j] = gs[i];
        WnA[kg * H + j] = gn[i];
    }
    float bias = bself[tx] + bneigh[tx];
    float* o = use_hout ? hout : g_hB;
    int ntiles = (N_ + 3) / 4;
    for (int tile = blockIdx.x; tile < ntiles; tile += gridDim.x) {
        __syncthreads();
        int n = tile * 4 + ty;
        if (n < N_) {
            ((float*)hs4)[t] = hin[(size_t)n * H + tx];
            ((float*)ns4)[t] = g_neigh[(size_t)n * H + tx];  // mean precomputed
        }
        __syncthreads();
        if (n < N_) {
            float acc = bias;
            #pragma unroll
            for (int kg = 0; kg < 16; kg++) {
                float4 hv = hs4[ty][kg];
                float4 nv = ns4[ty][kg];
                float4 ws = WsA[kg * H + tx];
                float4 wn = WnA[kg * H + tx];
                acc += hv.x * ws.x + hv.y * ws.y + hv.z * ws.z + hv.w * ws.w
                     + nv.x * wn.x + nv.y * wn.y + nv.z * wn.z + nv.w * wn.w;
            }
            o[(size_t)n * H + tx] = fmaxf(acc, 0.f);
        }
    }
}

// ---------------- launch ----------------
extern "C" void kernel_launch(void* const* d_in, const int* in_sizes, int n_in,
                              void* d_out, int out_size) {
    const float* node_feats = (const float*)d_in[0];
    const float* edge_feats = (const float*)d_in[1];
    const float* enc        = (const float*)d_in[2];
    const int*   ei         = (const int*)d_in[3];
    const float* Wn     = (const float*)d_in[4];
    const float* bn     = (const float*)d_in[5];
    const float* We     = (const float*)d_in[6];
    const float* be     = (const float*)d_in[7];
    const float* Wself  = (const float*)d_in[8];   // (2,64,64)
    const float* bself  = (const float*)d_in[9];   // (2,64)
    const float* Wneigh = (const float*)d_in[10];
    const float* bneigh = (const float*)d_in[11];
    const float* Wa     = (const float*)d_in[12];
    const float* ba     = (const float*)d_in[13];
    const float* W1     = (const float*)d_in[14];
    const float* b1     = (const float*)d_in[15];
    const float* W2     = (const float*)d_in[16];
    const float* b2     = (const float*)d_in[17];

    int N_ = in_sizes[0] / 3;
    int E_ = in_sizes[1] / 3;
    float* out = (float*)d_out;
    float* h_out = out + E_;  // output = [scores (E), h (N*64)]

    int n64 = N_ * H;
    dim3 cdim(64, 4);
    int cgrid = 888;
    int agrid = (N_ * 32 + 255) / 256;  // warp per node, 256-thread blocks

    // 1. zero degree counters
    k_zero_cnt<<<(N_ + 255) / 256, 256>>>(N_);
    // 2. fused edge constants
    k_pre<<<1, 64>>>(enc, Wa, ba, We, be);
    // 3. node_fc
    k_nodefc<<<(n64 + 255) / 256, 256>>>(node_feats, Wn, bn, N_);
    // 4. edge scorer (counts degrees) -> out[0:E]
    k_scorer<<<(E_ + 255) / 256, 128>>>(edge_feats, ei, W1, b1, W2, b2, out, E_);
    // 5. CSR build (once)
    k_scan<<<1, 1024>>>(N_);
    k_fill<<<(E_ + 255) / 256, 256>>>(ei, E_);
    // 6. layer 0: gather-mean from hA, combine -> hB
    k_agg<<<agrid, 256>>>(0, N_);
    k_combine<<<cgrid, cdim>>>(Wself, bself, Wneigh, bneigh, nullptr, 0, 0, N_);
    // 7. layer 1: gather-mean from hB, combine -> d_out h region
    k_agg<<<agrid, 256>>>(1, N_);
    k_combine<<<cgrid, cdim>>>(Wself + H * H, bself + H,
                               Wneigh + H * H, bneigh + H,
                               h_out, 1, 1, N_);
}

// round 12
// speedup vs baseline: 2.2860x; 1.3634x over previous
#include <cuda_runtime.h>
#include <cuda_bf16.h>
#include <cstdint>

#define MAXN 50000
#define MAXE 1600000
#define H 64

typedef unsigned long long ull;

// ---------------- device scratch (no allocation allowed) ----------------
__device__ float g_hA[MAXN * H];     // node embeddings ping
__device__ float g_hB[MAXN * H];     // node embeddings pong
__device__ float g_neigh[MAXN * H];  // neighbor MEAN per node
__device__ int   g_cnt[MAXN];        // out-degree (segment counts over src)
__device__ int   g_off[MAXN];        // CSR row offsets (exclusive scan of cnt)
__device__ int   g_cur[MAXN];        // fill cursors
__device__ int   g_adj[MAXE];        // CSR adjacency: dst lists grouped by src
__device__ ull   g_ec2[4 * 32];      // fused edge consts, f32x2-packed

// ---------------- f32x2 helpers (packed fp32, sm_100+) ----------------
__device__ __forceinline__ ull pack2(float lo, float hi) {
    ull d; asm("mov.b64 %0, {%1,%2};" : "=l"(d) : "f"(lo), "f"(hi)); return d;
}
__device__ __forceinline__ void unpack2(ull v, float& lo, float& hi) {
    asm("mov.b64 {%0,%1}, %2;" : "=f"(lo), "=f"(hi) : "l"(v));
}
__device__ __forceinline__ ull fma2(ull a, ull b, ull c) {
    ull d; asm("fma.rn.f32x2 %0, %1, %2, %3;" : "=l"(d) : "l"(a), "l"(b), "l"(c));
    return d;
}

// ---------------- bf16 split helpers ----------------
// pack pair (even=low half, odd=high half) into bf16x2; hi part + residual part
__device__ __forceinline__ void split_pair(float even, float odd,
                                           uint32_t& hp, uint32_t& lp) {
    asm("cvt.rn.bf16x2.f32 %0, %1, %2;" : "=r"(hp) : "f"(odd), "f"(even));
    float he = __uint_as_float(hp << 16);
    float ho = __uint_as_float(hp & 0xffff0000u);
    float re = even - he, ro = odd - ho;
    asm("cvt.rn.bf16x2.f32 %0, %1, %2;" : "=r"(lp) : "f"(ro), "f"(re));
}

__device__ __forceinline__ uint32_t smem_u32(const void* p) {
    uint32_t a;
    asm("{ .reg .u64 t; cvta.to.shared.u64 t, %1; cvt.u32.u64 %0, t; }"
        : "=r"(a) : "l"(p));
    return a;
}

#define SMEM_SWZ(o) ((o) ^ (((o) >> 3) & 0x70))

__device__ __forceinline__ void ldmx4(uint32_t& r0, uint32_t& r1,
                                      uint32_t& r2, uint32_t& r3, uint32_t addr) {
    asm volatile("ldmatrix.sync.aligned.m8n8.x4.shared.b16 {%0,%1,%2,%3}, [%4];"
                 : "=r"(r0), "=r"(r1), "=r"(r2), "=r"(r3) : "r"(addr));
}
__device__ __forceinline__ void mma_bf16(float* d, const uint32_t* a,
                                         uint32_t b0, uint32_t b1) {
    asm volatile(
        "mma.sync.aligned.m16n8k16.row.col.f32.bf16.bf16.f32 "
        "{%0,%1,%2,%3}, {%4,%5,%6,%7}, {%8,%9}, {%0,%1,%2,%3};"
        : "+f"(d[0]), "+f"(d[1]), "+f"(d[2]), "+f"(d[3])
        : "r"(a[0]), "r"(a[1]), "r"(a[2]), "r"(a[3]), "r"(b0), "r"(b1));
}

// ---------------- zero degree counters ----------------
__global__ void k_zero_cnt(int n) {
    int i = blockIdx.x * blockDim.x + threadIdx.x;
    if (i < n) g_cnt[i] = 0;
}

// ---------------- precompute fused edge constants (packed) ----------------
__global__ void k_pre(const float* __restrict__ enc, const float* __restrict__ Wa,
                      const float* __restrict__ ba, const float* __restrict__ We,
                      const float* __restrict__ be) {
    __shared__ float vm[H];
    __shared__ float4 ecs[H];
    int j = threadIdx.x;  // 64 threads
    float s = 0.f;
    #pragma unroll
    for (int v = 0; v < 16; v++) s += enc[v * H + j];
    vm[j] = s * (1.f / 16.f);
    __syncthreads();
    const float* wr = Wa + j * 128;
    float m0 = 0.f, m1 = 0.f, m2 = 0.f, c = ba[j];
    #pragma unroll 8
    for (int m = 0; m < H; m++) {
        float w = wr[m];
        m0 += w * We[m * 3 + 0];
        m1 += w * We[m * 3 + 1];
        m2 += w * We[m * 3 + 2];
        c  += w * be[m];
    }
    #pragma unroll 8
    for (int d = 0; d < H; d++) c += wr[H + d] * vm[d];
    ecs[j] = make_float4(m0, m1, m2, c);
    __syncthreads();
    if (j < 32) {
        float4 lo = ecs[2 * j], hi = ecs[2 * j + 1];
        g_ec2[0 * 32 + j] = pack2(lo.x, hi.x);
        g_ec2[1 * 32 + j] = pack2(lo.y, hi.y);
        g_ec2[2 * 32 + j] = pack2(lo.z, hi.z);
        g_ec2[3 * 32 + j] = pack2(lo.w, hi.w);
    }
}

// ---------------- node_fc: h = node_feats @ Wn.T + bn ----------------
__global__ void k_nodefc(const float* __restrict__ nf, const float* __restrict__ Wn,
                         const float* __restrict__ bn, int N_) {
    __shared__ float Ws[H * 3];
    __shared__ float bs[H];
    int t = threadIdx.x;
    if (t < H * 3) Ws[t] = Wn[t];
    if (t < H) bs[t] = bn[t];
    __syncthreads();
    int idx = blockIdx.x * blockDim.x + t;
    if (idx >= N_ * H) return;
    int n = idx >> 6, j = idx & 63;
    float f0 = nf[n * 3 + 0], f1 = nf[n * 3 + 1], f2 = nf[n * 3 + 2];
    g_hA[idx] = Ws[j * 3 + 0] * f0 + Ws[j * 3 + 1] * f1 + Ws[j * 3 + 2] * f2 + bs[j];
}

// ---------------- tensor-core edge scorer (mma.sync bf16 split) -------------
// Per warp-tile (32 edges): a = relu(M1 ef + c1) fp32 -> bf16 hi/lo in smem;
// D = Ahi*Whi + Alo*Whi + Ahi*Wlo via mma.sync.m16n8k16 (err ~2^-16);
// score = b2 + w2 . relu(D + b1). Warps fully independent (no block sync
// in loop). Persistent CTAs; W1 hi/lo split once per block.
__global__ void __launch_bounds__(128) k_scorer_mma(
    const float* __restrict__ ef, const int* __restrict__ srcarr,
    const float* __restrict__ W1, const float* __restrict__ b1,
    const float* __restrict__ W2, const float* __restrict__ b2,
    float* __restrict__ out, int E_)
{
    extern __shared__ char dsm[];
    __shared__ ull ec2s[128];
    __shared__ float b1s[H], w2s[H];
    __shared__ float b2s;

    int t = threadIdx.x;
    int wid = t >> 5, lane = t & 31;

    char* p = (char*)(((size_t)dsm + 1023) & ~(size_t)1023);
    char* Ahi = p;                 // 128 rows x 128B (bf16 hi), swizzled
    char* Alo = p + 16384;
    char* Whi = p + 32768;         // 64 rows (n) x 128B (bf16 hi of W1[n][k])
    char* Wlo = p + 40960;

    ec2s[t] = g_ec2[t];
    if (t < H) { b1s[t] = b1[t]; w2s[t] = W2[t]; }
    if (t == 0) b2s = b2[0];

    // split W1 into bf16 hi/lo (row-major n x k, swizzled 128B rows)
    for (int i = t; i < 2048; i += 128) {
        int r = i >> 5, c = i & 31;  // row n, float-pair index
        float w0 = W1[r * 64 + 2 * c], w1v = W1[r * 64 + 2 * c + 1];
        uint32_t hp, lp;
        split_pair(w0, w1v, hp, lp);
        uint32_t off = SMEM_SWZ((uint32_t)(r * 128 + c * 4));
        *(uint32_t*)(Whi + off) = hp;
        *(uint32_t*)(Wlo + off) = lp;
    }
    __syncthreads();

    uint32_t AhiB = smem_u32(Ahi), AloB = smem_u32(Alo);
    uint32_t WhiB = smem_u32(Whi), WloB = smem_u32(Wlo);

    int l = lane & 7, sel = lane >> 3;
    int rowloc = wid * 32 + lane;              // this lane's A row (its edge)
    uint32_t rowbase = (uint32_t)(rowloc * 128);

    int wtiles = (E_ + 31) / 32;
    for (int wt = blockIdx.x * 4 + wid; wt < wtiles; wt += gridDim.x * 4) {
        int e = wt * 32 + lane;
        bool ve = (e < E_);
        int eS = ve ? e : (E_ - 1);
        if (ve) atomicAdd(&g_cnt[srcarr[e]], 1);

        // ---- a-phase: fp32 compute, relu, bf16 split, STS.128 ----
        float f0 = ef[eS * 3 + 0], f1 = ef[eS * 3 + 1], f2 = ef[eS * 3 + 2];
        ull f0p = pack2(f0, f0), f1p = pack2(f1, f1), f2p = pack2(f2, f2);
        #pragma unroll
        for (int g = 0; g < 8; g++) {
            uint32_t hw4[4], lw4[4];
            #pragma unroll
            for (int k = 0; k < 4; k++) {
                int q = g * 4 + k;
                ull v = fma2(ec2s[64 + q], f2p, ec2s[96 + q]);
                v = fma2(ec2s[32 + q], f1p, v);
                v = fma2(ec2s[q], f0p, v);
                float lo, hi; unpack2(v, lo, hi);
                lo = fmaxf(lo, 0.f); hi = fmaxf(hi, 0.f);
                split_pair(lo, hi, hw4[k], lw4[k]);
            }
            uint32_t off = SMEM_SWZ(rowbase + g * 16);
            *(uint4*)(Ahi + off) = make_uint4(hw4[0], hw4[1], hw4[2], hw4[3]);
            *(uint4*)(Alo + off) = make_uint4(lw4[0], lw4[1], lw4[2], lw4[3]);
        }
        __syncwarp();

        // ---- MMA: two m16 tiles over this warp's 32 rows ----
        #pragma unroll
        for (int mt = 0; mt < 2; mt++) {
            int Rloc = wid * 32 + mt * 16;     // smem row base
            // A fragments for 4 k-tiles (hi & lo)
            uint32_t ahi[4][4], alo[4][4];
            uint32_t arow = (uint32_t)(Rloc + l + ((sel & 1) << 3));
            #pragma unroll
            for (int kt = 0; kt < 4; kt++) {
                uint32_t acol = kt * 32 + ((sel & 2) ? 16 : 0);
                uint32_t aoff = SMEM_SWZ(arow * 128 + acol);
                ldmx4(ahi[kt][0], ahi[kt][1], ahi[kt][2], ahi[kt][3], AhiB + aoff);
                ldmx4(alo[kt][0], alo[kt][1], alo[kt][2], alo[kt][3], AloB + aoff);
            }

            float acc[8][4];
            #pragma unroll
            for (int nt = 0; nt < 8; nt++)
                #pragma unroll
                for (int c = 0; c < 4; c++) acc[nt][c] = 0.f;

            uint32_t wrow_l = (uint32_t)(l + ((sel & 2) ? 8 : 0));
            #pragma unroll
            for (int ntp = 0; ntp < 4; ntp++) {
                int nt0 = 2 * ntp, nt1 = 2 * ntp + 1;
                uint32_t wrow = (uint32_t)(ntp * 16) + wrow_l;
                #pragma unroll
                for (int kt = 0; kt < 4; kt++) {
                    uint32_t wcol = kt * 32 + ((sel & 1) ? 16 : 0);
                    uint32_t woff = SMEM_SWZ(wrow * 128 + wcol);
                    uint32_t wh0, wh1, wh2, wh3, wl0, wl1, wl2, wl3;
                    ldmx4(wh0, wh1, wh2, wh3, WhiB + woff);
                    ldmx4(wl0, wl1, wl2, wl3, WloB + woff);
                    mma_bf16(acc[nt0], ahi[kt], wh0, wh1);
                    mma_bf16(acc[nt1], ahi[kt], wh2, wh3);
                    mma_bf16(acc[nt0], alo[kt], wh0, wh1);
                    mma_bf16(acc[nt1], alo[kt], wh2, wh3);
                    mma_bf16(acc[nt0], ahi[kt], wl0, wl1);
                    mma_bf16(acc[nt1], ahi[kt], wl2, wl3);
                }
            }

            // ---- epilogue: score = b2 + w2 . relu(D + b1) ----
            int g = lane >> 2, q = lane & 3;
            float p0 = 0.f, p1 = 0.f;
            #pragma unroll
            for (int nt = 0; nt < 8; nt++) {
                int c0 = nt * 8 + q * 2;
                float bb0 = b1s[c0], bb1 = b1s[c0 + 1];
                float ww0 = w2s[c0], ww1 = w2s[c0 + 1];
                p0 += ww0 * fmaxf(acc[nt][0] + bb0, 0.f)
                    + ww1 * fmaxf(acc[nt][1] + bb1, 0.f);
                p1 += ww0 * fmaxf(acc[nt][2] + bb0, 0.f)
                    + ww1 * fmaxf(acc[nt][3] + bb1, 0.f);
            }
            p0 += __shfl_xor_sync(0xffffffffu, p0, 1);
            p0 += __shfl_xor_sync(0xffffffffu, p0, 2);
            p1 += __shfl_xor_sync(0xffffffffu, p1, 1);
            p1 += __shfl_xor_sync(0xffffffffu, p1, 2);
            if (q == 0) {
                int er0 = wt * 32 + mt * 16 + g;
                int er1 = er0 + 8;
                if (er0 < E_) out[er0] = b2s + p0;
                if (er1 < E_) out[er1] = b2s + p1;
            }
        }
        __syncwarp();   // all lanes done reading A before next iter's STS
    }
}

// ---------------- exclusive scan of g_cnt -> g_off, g_cur (single block) ------
__global__ __launch_bounds__(1024) void k_scan(int N_) {
    __shared__ int warpsum[32];
    __shared__ int warpoff[32];
    __shared__ int carry_s;
    int t = threadIdx.x, lane = t & 31, wid = t >> 5;
    if (t == 0) carry_s = 0;
    __syncthreads();
    for (int base = 0; base < N_; base += 1024) {
        int i = base + t;
        int v = (i < N_) ? g_cnt[i] : 0;
        int incl = v;
        #pragma unroll
        for (int off = 1; off < 32; off <<= 1) {
            int x = __shfl_up_sync(0xffffffffu, incl, off);
            if (lane >= off) incl += x;
        }
        if (lane == 31) warpsum[wid] = incl;
        __syncthreads();
        if (wid == 0) {
            int s = warpsum[lane];
            int si = s;
            #pragma unroll
            for (int off = 1; off < 32; off <<= 1) {
                int x = __shfl_up_sync(0xffffffffu, si, off);
                if (lane >= off) si += x;
            }
            warpoff[lane] = si - s;
        }
        __syncthreads();
        int excl = incl - v + warpoff[wid] + carry_s;
        if (i < N_) { g_off[i] = excl; g_cur[i] = excl; }
        __syncthreads();
        if (t == 0) carry_s += warpoff[31] + warpsum[31];
        __syncthreads();
    }
}

// ---------------- CSR fill: adj grouped by src ----------------
__global__ void k_fill(const int* __restrict__ ei, int E_) {
    int e = blockIdx.x * blockDim.x + threadIdx.x;
    if (e >= E_) return;
    int s = ei[e], d = ei[E_ + e];
    int pos = atomicAdd(&g_cur[s], 1);
    g_adj[pos] = d;
}

// ---------------- gather aggregation: neigh_mean per node (warp/node) --------
__global__ void k_agg(int which, int N_) {
    const float2* hin2 = (const float2*)(which ? g_hB : g_hA);
    int w = (blockIdx.x * blockDim.x + threadIdx.x) >> 5;
    int lane = threadIdx.x & 31;
    if (w >= N_) return;
    int beg = g_off[w], cnt = g_cnt[w];
    int end = beg + cnt;
    float ax = 0.f, ay = 0.f, bx = 0.f, by = 0.f;
    int i = beg;
    for (; i + 1 < end; i += 2) {
        int d0 = g_adj[i], d1 = g_adj[i + 1];
        float2 v0 = hin2[d0 * 32 + lane];
        float2 v1 = hin2[d1 * 32 + lane];
        ax += v0.x; ay += v0.y;
        bx += v1.x; by += v1.y;
    }
    if (i < end) {
        int d = g_adj[i];
        float2 v = hin2[d * 32 + lane];
        ax += v.x; ay += v.y;
    }
    float rd = (cnt > 0) ? 1.f / (float)cnt : 0.f;
    float2 o; o.x = (ax + bx) * rd; o.y = (ay + by) * rd;
    ((float2*)g_neigh)[w * 32 + lane] = o;
}

// ---------------- SAGE combine (persistent): h = relu(Wself@h + Wneigh@mean + b)
__global__ void k_combine(const float* __restrict__ Wself, const float* __restrict__ bself,
                          const float* __restrict__ Wneigh, const float* __restrict__ bneigh,
                          float* hout, int which_in, int use_hout, int N_) {
    const float* hin = which_in ? g_hB : g_hA;
    __shared__ float4 WsA[16 * H];  // [kg][j]
    __shared__ float4 WnA[16 * H];
    __shared__ float4 hs4[4][16];
    __shared__ float4 ns4[4][16];
    int tx = threadIdx.x, ty = threadIdx.y;
    int t = ty * 64 + tx;
    const float4* gs = (const float4*)Wself;
    const float4* gn = (const float4*)Wneigh;
    for (int i = t; i < H * 16; i += 256) {
        int j = i >> 4, kg = i & 15;
        WsA[kg * H + j] = gs[i];
        WnA[kg * H + j] = gn[i];
    }
    float bias = bself[tx] + bneigh[tx];
    float* o = use_hout ? hout : g_hB;
    int ntiles = (N_ + 3) / 4;
    for (int tile = blockIdx.x; tile < ntiles; tile += gridDim.x) {
        __syncthreads();
        int n = tile * 4 + ty;
        if (n < N_) {
            ((float*)hs4)[t] = hin[(size_t)n * H + tx];
            ((float*)ns4)[t] = g_neigh[(size_t)n * H + tx];
        }
        __syncthreads();
        if (n < N_) {
            float acc = bias;
            #pragma unroll
            for (int kg = 0; kg < 16; kg++) {
                float4 hv = hs4[ty][kg];
                float4 nv = ns4[ty][kg];
                float4 ws = WsA[kg * H + tx];
                float4 wn = WnA[kg * H + tx];
                acc += hv.x * ws.x + hv.y * ws.y + hv.z * ws.z + hv.w * ws.w
                     + nv.x * wn.x + nv.y * wn.y + nv.z * wn.z + nv.w * wn.w;
            }
            o[(size_t)n * H + tx] = fmaxf(acc, 0.f);
        }
    }
}

// ---------------- launch ----------------
extern "C" void kernel_launch(void* const* d_in, const int* in_sizes, int n_in,
                              void* d_out, int out_size) {
    const float* node_feats = (const float*)d_in[0];
    const float* edge_feats = (const float*)d_in[1];
    const float* enc        = (const float*)d_in[2];
    const int*   ei         = (const int*)d_in[3];
    const float* Wn     = (const float*)d_in[4];
    const float* bn     = (const float*)d_in[5];
    const float* We     = (const float*)d_in[6];
    const float* be     = (const float*)d_in[7];
    const float* Wself  = (const float*)d_in[8];   // (2,64,64)
    const float* bself  = (const float*)d_in[9];   // (2,64)
    const float* Wneigh = (const float*)d_in[10];
    const float* bneigh = (const float*)d_in[11];
    const float* Wa     = (const float*)d_in[12];
    const float* ba     = (const float*)d_in[13];
    const float* W1     = (const float*)d_in[14];
    const float* b1     = (const float*)d_in[15];
    const float* W2     = (const float*)d_in[16];
    const float* b2     = (const float*)d_in[17];

    int N_ = in_sizes[0] / 3;
    int E_ = in_sizes[1] / 3;
    float* out = (float*)d_out;
    float* h_out = out + E_;  // output = [scores (E), h (N*64)]

    int n64 = N_ * H;
    dim3 cdim(64, 4);
    int cgrid = 888;
    int agrid = (N_ * 32 + 255) / 256;

    int wtiles = (E_ + 31) / 32;
    int sgrid = (wtiles + 3) / 4;
    if (sgrid > 592) sgrid = 592;                // 4 persistent CTAs/SM
    int dyn_smem = 50176;                        // 48K tiles + 1K align slack
    cudaFuncSetAttribute(k_scorer_mma,
                         cudaFuncAttributeMaxDynamicSharedMemorySize, dyn_smem);

    // 1. zero degree counters
    k_zero_cnt<<<(N_ + 255) / 256, 256>>>(N_);
    // 2. fused edge constants
    k_pre<<<1, 64>>>(enc, Wa, ba, We, be);
    // 3. node_fc
    k_nodefc<<<(n64 + 255) / 256, 256>>>(node_feats, Wn, bn, N_);
    // 4. tensor-core edge scorer (counts degrees) -> out[0:E]
    k_scorer_mma<<<sgrid, 128, dyn_smem>>>(edge_feats, ei, W1, b1, W2, b2,
                                           out, E_);
    // 5. CSR build (once)
    k_scan<<<1, 1024>>>(N_);
    k_fill<<<(E_ + 255) / 256, 256>>>(ei, E_);
    // 6. layer 0: gather-mean from hA, combine -> hB
    k_agg<<<agrid, 256>>>(0, N_);
    k_combine<<<cgrid, cdim>>>(Wself, bself, Wneigh, bneigh, nullptr, 0, 0, N_);
    // 7. layer 1: gather-mean from hB, combine -> d_out h region
    k_agg<<<agrid, 256>>>(1, N_);
    k_combine<<<cgrid, cdim>>>(Wself + H * H, bself + H,
                               Wneigh + H * H, bneigh + H,
                               h_out, 1, 1, N_);
}

// round 13
// speedup vs baseline: 2.4395x; 1.0671x over previous
#include <cuda_runtime.h>
#include <cuda_bf16.h>
#include <cstdint>

#define MAXN 50000
#define MAXE 1600000
#define H 64

typedef unsigned long long ull;

// ---------------- device scratch (no allocation allowed) ----------------
__device__ float g_hA[MAXN * H];     // node embeddings ping
__device__ float g_hB[MAXN * H];     // node embeddings pong
__device__ float g_neigh[MAXN * H];  // neighbor MEAN per node
__device__ int   g_cnt[MAXN];        // out-degree (segment counts over src)
__device__ int   g_off[MAXN];        // CSR row offsets (exclusive scan of cnt)
__device__ int   g_cur[MAXN];        // fill cursors
__device__ int   g_adj[MAXE];        // CSR adjacency: dst lists grouped by src
__device__ ull   g_ec2[4 * 32];      // fused edge consts, f32x2-packed

// ---------------- f32x2 helpers (packed fp32, sm_100+) ----------------
__device__ __forceinline__ ull pack2(float lo, float hi) {
    ull d; asm("mov.b64 %0, {%1,%2};" : "=l"(d) : "f"(lo), "f"(hi)); return d;
}
__device__ __forceinline__ void unpack2(ull v, float& lo, float& hi) {
    asm("mov.b64 {%0,%1}, %2;" : "=f"(lo), "=f"(hi) : "l"(v));
}
__device__ __forceinline__ ull fma2(ull a, ull b, ull c) {
    ull d; asm("fma.rn.f32x2 %0, %1, %2, %3;" : "=l"(d) : "l"(a), "l"(b), "l"(c));
    return d;
}

// ---------------- bf16 split helpers ----------------
__device__ __forceinline__ void split_pair(float even, float odd,
                                           uint32_t& hp, uint32_t& lp) {
    asm("cvt.rn.bf16x2.f32 %0, %1, %2;" : "=r"(hp) : "f"(odd), "f"(even));
    float he = __uint_as_float(hp << 16);
    float ho = __uint_as_float(hp & 0xffff0000u);
    float re = even - he, ro = odd - ho;
    asm("cvt.rn.bf16x2.f32 %0, %1, %2;" : "=r"(lp) : "f"(ro), "f"(re));
}

__device__ __forceinline__ uint32_t smem_u32(const void* p) {
    uint32_t a;
    asm("{ .reg .u64 t; cvta.to.shared.u64 t, %1; cvt.u32.u64 %0, t; }"
        : "=r"(a) : "l"(p));
    return a;
}

#define SMEM_SWZ(o) ((o) ^ (((o) >> 3) & 0x70))

__device__ __forceinline__ void ldmx4(uint32_t& r0, uint32_t& r1,
                                      uint32_t& r2, uint32_t& r3, uint32_t addr) {
    asm volatile("ldmatrix.sync.aligned.m8n8.x4.shared.b16 {%0,%1,%2,%3}, [%4];"
                 : "=r"(r0), "=r"(r1), "=r"(r2), "=r"(r3) : "r"(addr));
}
__device__ __forceinline__ void mma_bf16(float* d, const uint32_t* a,
                                         uint32_t b0, uint32_t b1) {
    asm volatile(
        "mma.sync.aligned.m16n8k16.row.col.f32.bf16.bf16.f32 "
        "{%0,%1,%2,%3}, {%4,%5,%6,%7}, {%8,%9}, {%0,%1,%2,%3};"
        : "+f"(d[0]), "+f"(d[1]), "+f"(d[2]), "+f"(d[3])
        : "r"(a[0]), "r"(a[1]), "r"(a[2]), "r"(a[3]), "r"(b0), "r"(b1));
}

// ---------------- fused init: pre (block 0) + nodefc + cnt zero -------------
__global__ void k_init(const float* __restrict__ nf, const float* __restrict__ Wn,
                       const float* __restrict__ bn, const float* __restrict__ enc,
                       const float* __restrict__ Wa, const float* __restrict__ ba,
                       const float* __restrict__ We, const float* __restrict__ be,
                       int N_) {
    if (blockIdx.x == 0) {
        // --- fused edge constants (64 working threads; all 256 hit syncs) ---
        __shared__ float vm[H];
        __shared__ float4 ecs[H];
        int j = threadIdx.x;
        if (j < H) {
            float s = 0.f;
            #pragma unroll
            for (int v = 0; v < 16; v++) s += enc[v * H + j];
            vm[j] = s * (1.f / 16.f);
        }
        __syncthreads();
        if (j < H) {
            const float* wr = Wa + j * 128;
            float m0 = 0.f, m1 = 0.f, m2 = 0.f, c = ba[j];
            #pragma unroll 8
            for (int m = 0; m < H; m++) {
                float w = wr[m];
                m0 += w * We[m * 3 + 0];
                m1 += w * We[m * 3 + 1];
                m2 += w * We[m * 3 + 2];
                c  += w * be[m];
            }
            #pragma unroll 8
            for (int d = 0; d < H; d++) c += wr[H + d] * vm[d];
            ecs[j] = make_float4(m0, m1, m2, c);
        }
        __syncthreads();
        if (j < 32) {
            float4 lo = ecs[2 * j], hi = ecs[2 * j + 1];
            g_ec2[0 * 32 + j] = pack2(lo.x, hi.x);
            g_ec2[1 * 32 + j] = pack2(lo.y, hi.y);
            g_ec2[2 * 32 + j] = pack2(lo.z, hi.z);
            g_ec2[3 * 32 + j] = pack2(lo.w, hi.w);
        }
        return;
    }
    // --- node_fc + degree-counter zeroing ---
    __shared__ float Ws[H * 3];
    __shared__ float bs[H];
    int t = threadIdx.x;
    if (t < H * 3) Ws[t] = Wn[t];
    if (t < H) bs[t] = bn[t];
    __syncthreads();
    int idx = (blockIdx.x - 1) * blockDim.x + t;
    if (idx < N_) g_cnt[idx] = 0;
    if (idx >= N_ * H) return;
    int n = idx >> 6, j = idx & 63;
    float f0 = nf[n * 3 + 0], f1 = nf[n * 3 + 1], f2 = nf[n * 3 + 2];
    g_hA[idx] = Ws[j * 3 + 0] * f0 + Ws[j * 3 + 1] * f1 + Ws[j * 3 + 2] * f2 + bs[j];
}

// ---------------- tensor-core edge scorer (mma.sync bf16 split) -------------
// UNCHANGED from R12 (148us, tensor=50%): protect the win.
__global__ void __launch_bounds__(128) k_scorer_mma(
    const float* __restrict__ ef, const int* __restrict__ srcarr,
    const float* __restrict__ W1, const float* __restrict__ b1,
    const float* __restrict__ W2, const float* __restrict__ b2,
    float* __restrict__ out, int E_)
{
    extern __shared__ char dsm[];
    __shared__ ull ec2s[128];
    __shared__ float b1s[H], w2s[H];
    __shared__ float b2s;

    int t = threadIdx.x;
    int wid = t >> 5, lane = t & 31;

    char* p = (char*)(((size_t)dsm + 1023) & ~(size_t)1023);
    char* Ahi = p;                 // 128 rows x 128B (bf16 hi), swizzled
    char* Alo = p + 16384;
    char* Whi = p + 32768;         // 64 rows (n) x 128B (bf16 hi of W1[n][k])
    char* Wlo = p + 40960;

    ec2s[t] = g_ec2[t];
    if (t < H) { b1s[t] = b1[t]; w2s[t] = W2[t]; }
    if (t == 0) b2s = b2[0];

    for (int i = t; i < 2048; i += 128) {
        int r = i >> 5, c = i & 31;
        float w0 = W1[r * 64 + 2 * c], w1v = W1[r * 64 + 2 * c + 1];
        uint32_t hp, lp;
        split_pair(w0, w1v, hp, lp);
        uint32_t off = SMEM_SWZ((uint32_t)(r * 128 + c * 4));
        *(uint32_t*)(Whi + off) = hp;
        *(uint32_t*)(Wlo + off) = lp;
    }
    __syncthreads();

    uint32_t AhiB = smem_u32(Ahi), AloB = smem_u32(Alo);
    uint32_t WhiB = smem_u32(Whi), WloB = smem_u32(Wlo);

    int l = lane & 7, sel = lane >> 3;
    int rowloc = wid * 32 + lane;
    uint32_t rowbase = (uint32_t)(rowloc * 128);

    int wtiles = (E_ + 31) / 32;
    for (int wt = blockIdx.x * 4 + wid; wt < wtiles; wt += gridDim.x * 4) {
        int e = wt * 32 + lane;
        bool ve = (e < E_);
        int eS = ve ? e : (E_ - 1);
        if (ve) atomicAdd(&g_cnt[srcarr[e]], 1);

        float f0 = ef[eS * 3 + 0], f1 = ef[eS * 3 + 1], f2 = ef[eS * 3 + 2];
        ull f0p = pack2(f0, f0), f1p = pack2(f1, f1), f2p = pack2(f2, f2);
        #pragma unroll
        for (int g = 0; g < 8; g++) {
            uint32_t hw4[4], lw4[4];
            #pragma unroll
            for (int k = 0; k < 4; k++) {
                int q = g * 4 + k;
                ull v = fma2(ec2s[64 + q], f2p, ec2s[96 + q]);
                v = fma2(ec2s[32 + q], f1p, v);
                v = fma2(ec2s[q], f0p, v);
                float lo, hi; unpack2(v, lo, hi);
                lo = fmaxf(lo, 0.f); hi = fmaxf(hi, 0.f);
                split_pair(lo, hi, hw4[k], lw4[k]);
            }
            uint32_t off = SMEM_SWZ(rowbase + g * 16);
            *(uint4*)(Ahi + off) = make_uint4(hw4[0], hw4[1], hw4[2], hw4[3]);
            *(uint4*)(Alo + off) = make_uint4(lw4[0], lw4[1], lw4[2], lw4[3]);
        }
        __syncwarp();

        #pragma unroll
        for (int mt = 0; mt < 2; mt++) {
            int Rloc = wid * 32 + mt * 16;
            uint32_t ahi[4][4], alo[4][4];
            uint32_t arow = (uint32_t)(Rloc + l + ((sel & 1) << 3));
            #pragma unroll
            for (int kt = 0; kt < 4; kt++) {
                uint32_t acol = kt * 32 + ((sel & 2) ? 16 : 0);
                uint32_t aoff = SMEM_SWZ(arow * 128 + acol);
                ldmx4(ahi[kt][0], ahi[kt][1], ahi[kt][2], ahi[kt][3], AhiB + aoff);
                ldmx4(alo[kt][0], alo[kt][1], alo[kt][2], alo[kt][3], AloB + aoff);
            }

            float acc[8][4];
            #pragma unroll
            for (int nt = 0; nt < 8; nt++)
                #pragma unroll
                for (int c = 0; c < 4; c++) acc[nt][c] = 0.f;

            uint32_t wrow_l = (uint32_t)(l + ((sel & 2) ? 8 : 0));
            #pragma unroll
            for (int ntp = 0; ntp < 4; ntp++) {
                int nt0 = 2 * ntp, nt1 = 2 * ntp + 1;
                uint32_t wrow = (uint32_t)(ntp * 16) + wrow_l;
                #pragma unroll
                for (int kt = 0; kt < 4; kt++) {
                    uint32_t wcol = kt * 32 + ((sel & 1) ? 16 : 0);
                    uint32_t woff = SMEM_SWZ(wrow * 128 + wcol);
                    uint32_t wh0, wh1, wh2, wh3, wl0, wl1, wl2, wl3;
                    ldmx4(wh0, wh1, wh2, wh3, WhiB + woff);
                    ldmx4(wl0, wl1, wl2, wl3, WloB + woff);
                    mma_bf16(acc[nt0], ahi[kt], wh0, wh1);
                    mma_bf16(acc[nt1], ahi[kt], wh2, wh3);
                    mma_bf16(acc[nt0], alo[kt], wh0, wh1);
                    mma_bf16(acc[nt1], alo[kt], wh2, wh3);
                    mma_bf16(acc[nt0], ahi[kt], wl0, wl1);
                    mma_bf16(acc[nt1], ahi[kt], wl2, wl3);
                }
            }

            int g = lane >> 2, q = lane & 3;
            float p0 = 0.f, p1 = 0.f;
            #pragma unroll
            for (int nt = 0; nt < 8; nt++) {
                int c0 = nt * 8 + q * 2;
                float bb0 = b1s[c0], bb1 = b1s[c0 + 1];
                float ww0 = w2s[c0], ww1 = w2s[c0 + 1];
                p0 += ww0 * fmaxf(acc[nt][0] + bb0, 0.f)
                    + ww1 * fmaxf(acc[nt][1] + bb1, 0.f);
                p1 += ww0 * fmaxf(acc[nt][2] + bb0, 0.f)
                    + ww1 * fmaxf(acc[nt][3] + bb1, 0.f);
            }
            p0 += __shfl_xor_sync(0xffffffffu, p0, 1);
            p0 += __shfl_xor_sync(0xffffffffu, p0, 2);
            p1 += __shfl_xor_sync(0xffffffffu, p1, 1);
            p1 += __shfl_xor_sync(0xffffffffu, p1, 2);
            if (q == 0) {
                int er0 = wt * 32 + mt * 16 + g;
                int er1 = er0 + 8;
                if (er0 < E_) out[er0] = b2s + p0;
                if (er1 < E_) out[er1] = b2s + p1;
            }
        }
        __syncwarp();
    }
}

// ---------------- exclusive scan of g_cnt (4 elems/thread, int4) ------------
__global__ __launch_bounds__(1024) void k_scan(int N_) {
    __shared__ int warpsum[32];
    __shared__ int warpoff[32];
    __shared__ int carry_s;
    int t = threadIdx.x, lane = t & 31, wid = t >> 5;
    if (t == 0) carry_s = 0;
    __syncthreads();
    for (int base = 0; base < N_; base += 4096) {
        int i0 = base + t * 4;
        int v0 = 0, v1 = 0, v2 = 0, v3 = 0;
        if (i0 + 3 < N_) {
            int4 q = *(const int4*)&g_cnt[i0];
            v0 = q.x; v1 = q.y; v2 = q.z; v3 = q.w;
        } else {
            if (i0 < N_)     v0 = g_cnt[i0];
            if (i0 + 1 < N_) v1 = g_cnt[i0 + 1];
            if (i0 + 2 < N_) v2 = g_cnt[i0 + 2];
            if (i0 + 3 < N_) v3 = g_cnt[i0 + 3];
        }
        int sum = v0 + v1 + v2 + v3;
        int incl = sum;
        #pragma unroll
        for (int off = 1; off < 32; off <<= 1) {
            int x = __shfl_up_sync(0xffffffffu, incl, off);
            if (lane >= off) incl += x;
        }
        if (lane == 31) warpsum[wid] = incl;
        __syncthreads();
        if (wid == 0) {
            int s = warpsum[lane];
            int si = s;
            #pragma unroll
            for (int off = 1; off < 32; off <<= 1) {
                int x = __shfl_up_sync(0xffffffffu, si, off);
                if (lane >= off) si += x;
            }
            warpoff[lane] = si - s;
        }
        __syncthreads();
        int o0 = incl - sum + warpoff[wid] + carry_s;
        int o1 = o0 + v0, o2 = o1 + v1, o3 = o2 + v2;
        if (i0 + 3 < N_) {
            *(int4*)&g_off[i0] = make_int4(o0, o1, o2, o3);
            *(int4*)&g_cur[i0] = make_int4(o0, o1, o2, o3);
        } else {
            if (i0 < N_)     { g_off[i0] = o0;     g_cur[i0] = o0; }
            if (i0 + 1 < N_) { g_off[i0 + 1] = o1; g_cur[i0 + 1] = o1; }
            if (i0 + 2 < N_) { g_off[i0 + 2] = o2; g_cur[i0 + 2] = o2; }
            if (i0 + 3 < N_) { g_off[i0 + 3] = o3; g_cur[i0 + 3] = o3; }
        }
        __syncthreads();
        if (t == 0) carry_s += warpoff[31] + warpsum[31];
        __syncthreads();
    }
}

// ---------------- CSR fill: adj grouped by src (2 edges/thread) --------------
__global__ void k_fill(const int* __restrict__ ei, int E_) {
    int e = (blockIdx.x * blockDim.x + threadIdx.x) * 2;
    if (e >= E_) return;
    int s0 = ei[e], d0 = ei[E_ + e];
    int p0 = atomicAdd(&g_cur[s0], 1);
    g_adj[p0] = d0;
    if (e + 1 < E_) {
        int s1 = ei[e + 1], d1 = ei[E_ + e + 1];
        int p1 = atomicAdd(&g_cur[s1], 1);
        g_adj[p1] = d1;
    }
}

// ---------------- gather aggregation: 16 lanes/node, float4, unroll 4 --------
__global__ void k_agg(int which, int N_) {
    const float4* hin4 = (const float4*)(which ? g_hB : g_hA);
    int gid = blockIdx.x * blockDim.x + threadIdx.x;
    int node = gid >> 4, lane = gid & 15;
    if (node >= N_) return;
    int beg = g_off[node], cnt = g_cnt[node];
    int end = beg + cnt;
    float4 a0 = make_float4(0.f, 0.f, 0.f, 0.f);
    float4 a1 = a0, a2 = a0, a3 = a0;
    int i = beg;
    for (; i + 4 <= end; i += 4) {
        int d0 = g_adj[i], d1 = g_adj[i + 1], d2 = g_adj[i + 2], d3 = g_adj[i + 3];
        float4 v0 = hin4[d0 * 16 + lane];
        float4 v1 = hin4[d1 * 16 + lane];
        float4 v2 = hin4[d2 * 16 + lane];
        float4 v3 = hin4[d3 * 16 + lane];
        a0.x += v0.x; a0.y += v0.y; a0.z += v0.z; a0.w += v0.w;
        a1.x += v1.x; a1.y += v1.y; a1.z += v1.z; a1.w += v1.w;
        a2.x += v2.x; a2.y += v2.y; a2.z += v2.z; a2.w += v2.w;
        a3.x += v3.x; a3.y += v3.y; a3.z += v3.z; a3.w += v3.w;
    }
    for (; i < end; i++) {
        int d = g_adj[i];
        float4 v = hin4[d * 16 + lane];
        a0.x += v.x; a0.y += v.y; a0.z += v.z; a0.w += v.w;
    }
    float rd = (cnt > 0) ? 1.f / (float)cnt : 0.f;
    float4 o;
    o.x = (a0.x + a1.x + a2.x + a3.x) * rd;
    o.y = (a0.y + a1.y + a2.y + a3.y) * rd;
    o.z = (a0.z + a1.z + a2.z + a3.z) * rd;
    o.w = (a0.w + a1.w + a2.w + a3.w) * rd;
    ((float4*)g_neigh)[node * 16 + lane] = o;
}

// ---------------- SAGE combine (persistent): h = relu(Wself@h + Wneigh@mean + b)
__global__ void k_combine(const float* __restrict__ Wself, const float* __restrict__ bself,
                          const float* __restrict__ Wneigh, const float* __restrict__ bneigh,
                          float* hout, int which_in, int use_hout, int N_) {
    const float* hin = which_in ? g_hB : g_hA;
    __shared__ float4 WsA[16 * H];  // [kg][j]
    __shared__ float4 WnA[16 * H];
    __shared__ float4 hs4[4][16];
    __shared__ float4 ns4[4][16];
    int tx = threadIdx.x, ty = threadIdx.y;
    int t = ty * 64 + tx;
    const float4* gs = (const float4*)Wself;
    const float4* gn = (const float4*)Wneigh;
    for (int i = t; i < H * 16; i += 256) {
        int j = i >> 4, kg = i & 15;
        WsA[kg * H + j] = gs[i];
        WnA[kg * H + j] = gn[i];
    }
    float bias = bself[tx] + bneigh[tx];
    float* o = use_hout ? hout : g_hB;
    int ntiles = (N_ + 3) / 4;
    for (int tile = blockIdx.x; tile < ntiles; tile += gridDim.x) {
        __syncthreads();
        int n = tile * 4 + ty;
        if (n < N_) {
            ((float*)hs4)[t] = hin[(size_t)n * H + tx];
            ((float*)ns4)[t] = g_neigh[(size_t)n * H + tx];
        }
        __syncthreads();
        if (n < N_) {
            float acc = bias;
            #pragma unroll
            for (int kg = 0; kg < 16; kg++) {
                float4 hv = hs4[ty][kg];
                float4 nv = ns4[ty][kg];
                float4 ws = WsA[kg * H + tx];
                float4 wn = WnA[kg * H + tx];
                acc += hv.x * ws.x + hv.y * ws.y + hv.z * ws.z + hv.w * ws.w
                     + nv.x * wn.x + nv.y * wn.y + nv.z * wn.z + nv.w * wn.w;
            }
            o[(size_t)n * H + tx] = fmaxf(acc, 0.f);
        }
    }
}

// ---------------- launch ----------------
extern "C" void kernel_launch(void* const* d_in, const int* in_sizes, int n_in,
                              void* d_out, int out_size) {
    const float* node_feats = (const float*)d_in[0];
    const float* edge_feats = (const float*)d_in[1];
    const float* enc        = (const float*)d_in[2];
    const int*   ei         = (const int*)d_in[3];
    const float* Wn     = (const float*)d_in[4];
    const float* bn     = (const float*)d_in[5];
    const float* We     = (const float*)d_in[6];
    const float* be     = (const float*)d_in[7];
    const float* Wself  = (const float*)d_in[8];   // (2,64,64)
    const float* bself  = (const float*)d_in[9];   // (2,64)
    const float* Wneigh = (const float*)d_in[10];
    const float* bneigh = (const float*)d_in[11];
    const float* Wa     = (const float*)d_in[12];
    const float* ba     = (const float*)d_in[13];
    const float* W1     = (const float*)d_in[14];
    const float* b1     = (const float*)d_in[15];
    const float* W2     = (const float*)d_in[16];
    const float* b2     = (const float*)d_in[17];

    int N_ = in_sizes[0] / 3;
    int E_ = in_sizes[1] / 3;
    float* out = (float*)d_out;
    float* h_out = out + E_;  // output = [scores (E), h (N*64)]

    int n64 = N_ * H;
    dim3 cdim(64, 4);
    int cgrid = 888;
    int agrid = (N_ * 16 + 255) / 256;          // 16 lanes per node

    int wtiles = (E_ + 31) / 32;
    int sgrid = (wtiles + 3) / 4;
    if (sgrid > 592) sgrid = 592;               // 4 persistent CTAs/SM
    int dyn_smem = 50176;
    cudaFuncSetAttribute(k_scorer_mma,
                         cudaFuncAttributeMaxDynamicSharedMemorySize, dyn_smem);

    // 1. fused init: pre + nodefc + cnt zero
    k_init<<<1 + (n64 + 255) / 256, 256>>>(node_feats, Wn, bn, enc, Wa, ba, We, be, N_);
    // 2. tensor-core edge scorer (counts degrees) -> out[0:E]
    k_scorer_mma<<<sgrid, 128, dyn_smem>>>(edge_feats, ei, W1, b1, W2, b2, out, E_);
    // 3. CSR build
    k_scan<<<1, 1024>>>(N_);
    k_fill<<<(E_ / 2 + 255) / 256, 256>>>(ei, E_);
    // 4. layer 0
    k_agg<<<agrid, 256>>>(0, N_);
    k_combine<<<cgrid, cdim>>>(Wself, bself, Wneigh, bneigh, nullptr, 0, 0, N_);
    // 5. layer 1
    k_agg<<<agrid, 256>>>(1, N_);
    k_combine<<<cgrid, cdim>>>(Wself + H * H, bself + H,
                               Wneigh + H * H, bneigh + H,
                               h_out, 1, 1, N_);
}

// round 14
// speedup vs baseline: 2.4410x; 1.0006x over previous
#include <cuda_runtime.h>
#include <cuda_bf16.h>
#include <cstdint>

#define MAXN 50000
#define MAXE 1600000
#define H 64

typedef unsigned long long ull;

// ---------------- device scratch (no allocation allowed) ----------------
__device__ float g_hA[MAXN * H];     // node embeddings ping
__device__ float g_hB[MAXN * H];     // node embeddings pong
__device__ float g_neigh[MAXN * H];  // neighbor MEAN per node
__device__ int   g_cnt[MAXN];        // out-degree (segment counts over src)
__device__ int   g_off[MAXN];        // CSR row offsets (exclusive scan of cnt)
__device__ int   g_cur[MAXN];        // fill cursors
__device__ int   g_adj[MAXE];        // CSR adjacency: dst lists grouped by src
__device__ ull   g_ec2[4 * 32];      // fused edge consts, f32x2-packed

// ---------------- f32x2 helpers (packed fp32, sm_100+) ----------------
__device__ __forceinline__ ull pack2(float lo, float hi) {
    ull d; asm("mov.b64 %0, {%1,%2};" : "=l"(d) : "f"(lo), "f"(hi)); return d;
}
__device__ __forceinline__ void unpack2(ull v, float& lo, float& hi) {
    asm("mov.b64 {%0,%1}, %2;" : "=f"(lo), "=f"(hi) : "l"(v));
}
__device__ __forceinline__ ull fma2(ull a, ull b, ull c) {
    ull d; asm("fma.rn.f32x2 %0, %1, %2, %3;" : "=l"(d) : "l"(a), "l"(b), "l"(c));
    return d;
}

// ---------------- bf16 split helpers ----------------
__device__ __forceinline__ void split_pair(float even, float odd,
                                           uint32_t& hp, uint32_t& lp) {
    asm("cvt.rn.bf16x2.f32 %0, %1, %2;" : "=r"(hp) : "f"(odd), "f"(even));
    float he = __uint_as_float(hp << 16);
    float ho = __uint_as_float(hp & 0xffff0000u);
    float re = even - he, ro = odd - ho;
    asm("cvt.rn.bf16x2.f32 %0, %1, %2;" : "=r"(lp) : "f"(ro), "f"(re));
}

__device__ __forceinline__ uint32_t smem_u32(const void* p) {
    uint32_t a;
    asm("{ .reg .u64 t; cvta.to.shared.u64 t, %1; cvt.u32.u64 %0, t; }"
        : "=r"(a) : "l"(p));
    return a;
}

#define SMEM_SWZ(o) ((o) ^ (((o) >> 3) & 0x70))

__device__ __forceinline__ void ldmx4(uint32_t& r0, uint32_t& r1,
                                      uint32_t& r2, uint32_t& r3, uint32_t addr) {
    asm volatile("ldmatrix.sync.aligned.m8n8.x4.shared.b16 {%0,%1,%2,%3}, [%4];"
                 : "=r"(r0), "=r"(r1), "=r"(r2), "=r"(r3) : "r"(addr));
}
__device__ __forceinline__ void mma_bf16(float* d, const uint32_t* a,
                                         uint32_t b0, uint32_t b1) {
    asm volatile(
        "mma.sync.aligned.m16n8k16.row.col.f32.bf16.bf16.f32 "
        "{%0,%1,%2,%3}, {%4,%5,%6,%7}, {%8,%9}, {%0,%1,%2,%3};"
        : "+f"(d[0]), "+f"(d[1]), "+f"(d[2]), "+f"(d[3])
        : "r"(a[0]), "r"(a[1]), "r"(a[2]), "r"(a[3]), "r"(b0), "r"(b1));
}

// ---------------- fused init: pre (block 0) + nodefc + cnt zero -------------
__global__ void k_init(const float* __restrict__ nf, const float* __restrict__ Wn,
                       const float* __restrict__ bn, const float* __restrict__ enc,
                       const float* __restrict__ Wa, const float* __restrict__ ba,
                       const float* __restrict__ We, const float* __restrict__ be,
                       int N_) {
    if (blockIdx.x == 0) {
        // --- fused edge constants (64 working threads; all 256 hit syncs) ---
        __shared__ float vm[H];
        __shared__ float4 ecs[H];
        int j = threadIdx.x;
        if (j < H) {
            float s = 0.f;
            #pragma unroll
            for (int v = 0; v < 16; v++) s += enc[v * H + j];
            vm[j] = s * (1.f / 16.f);
        }
        __syncthreads();
        if (j < H) {
            const float* wr = Wa + j * 128;
            float m0 = 0.f, m1 = 0.f, m2 = 0.f, c = ba[j];
            #pragma unroll 8
            for (int m = 0; m < H; m++) {
                float w = wr[m];
                m0 += w * We[m * 3 + 0];
                m1 += w * We[m * 3 + 1];
                m2 += w * We[m * 3 + 2];
                c  += w * be[m];
            }
            #pragma unroll 8
            for (int d = 0; d < H; d++) c += wr[H + d] * vm[d];
            ecs[j] = make_float4(m0, m1, m2, c);
        }
        __syncthreads();
        if (j < 32) {
            float4 lo = ecs[2 * j], hi = ecs[2 * j + 1];
            g_ec2[0 * 32 + j] = pack2(lo.x, hi.x);
            g_ec2[1 * 32 + j] = pack2(lo.y, hi.y);
            g_ec2[2 * 32 + j] = pack2(lo.z, hi.z);
            g_ec2[3 * 32 + j] = pack2(lo.w, hi.w);
        }
        return;
    }
    // --- node_fc + degree-counter zeroing ---
    __shared__ float Ws[H * 3];
    __shared__ float bs[H];
    int t = threadIdx.x;
    if (t < H * 3) Ws[t] = Wn[t];
    if (t < H) bs[t] = bn[t];
    __syncthreads();
    int idx = (blockIdx.x - 1) * blockDim.x + t;
    if (idx < N_) g_cnt[idx] = 0;
    if (idx >= N_ * H) return;
    int n = idx >> 6, j = idx & 63;
    float f0 = nf[n * 3 + 0], f1 = nf[n * 3 + 1], f2 = nf[n * 3 + 2];
    g_hA[idx] = Ws[j * 3 + 0] * f0 + Ws[j * 3 + 1] * f1 + Ws[j * 3 + 2] * f2 + bs[j];
}

// ---------------- tensor-core edge scorer (mma.sync bf16 split) -------------
// UNCHANGED from R12 (148us, tensor=50%): protect the win.
__global__ void __launch_bounds__(128) k_scorer_mma(
    const float* __restrict__ ef, const int* __restrict__ srcarr,
    const float* __restrict__ W1, const float* __restrict__ b1,
    const float* __restrict__ W2, const float* __restrict__ b2,
    float* __restrict__ out, int E_)
{
    extern __shared__ char dsm[];
    __shared__ ull ec2s[128];
    __shared__ float b1s[H], w2s[H];
    __shared__ float b2s;

    int t = threadIdx.x;
    int wid = t >> 5, lane = t & 31;

    char* p = (char*)(((size_t)dsm + 1023) & ~(size_t)1023);
    char* Ahi = p;                 // 128 rows x 128B (bf16 hi), swizzled
    char* Alo = p + 16384;
    char* Whi = p + 32768;         // 64 rows (n) x 128B (bf16 hi of W1[n][k])
    char* Wlo = p + 40960;

    ec2s[t] = g_ec2[t];
    if (t < H) { b1s[t] = b1[t]; w2s[t] = W2[t]; }
    if (t == 0) b2s = b2[0];

    for (int i = t; i < 2048; i += 128) {
        int r = i >> 5, c = i & 31;
        float w0 = W1[r * 64 + 2 * c], w1v = W1[r * 64 + 2 * c + 1];
        uint32_t hp, lp;
        split_pair(w0, w1v, hp, lp);
        uint32_t off = SMEM_SWZ((uint32_t)(r * 128 + c * 4));
        *(uint32_t*)(Whi + off) = hp;
        *(uint32_t*)(Wlo + off) = lp;
    }
    __syncthreads();

    uint32_t AhiB = smem_u32(Ahi), AloB = smem_u32(Alo);
    uint32_t WhiB = smem_u32(Whi), WloB = smem_u32(Wlo);

    int l = lane & 7, sel = lane >> 3;
    int rowloc = wid * 32 + lane;
    uint32_t rowbase = (uint32_t)(rowloc * 128);

    int wtiles = (E_ + 31) / 32;
    for (int wt = blockIdx.x * 4 + wid; wt < wtiles; wt += gridDim.x * 4) {
        int e = wt * 32 + lane;
        bool ve = (e < E_);
        int eS = ve ? e : (E_ - 1);
        if (ve) atomicAdd(&g_cnt[srcarr[e]], 1);

        float f0 = ef[eS * 3 + 0], f1 = ef[eS * 3 + 1], f2 = ef[eS * 3 + 2];
        ull f0p = pack2(f0, f0), f1p = pack2(f1, f1), f2p = pack2(f2, f2);
        #pragma unroll
        for (int g = 0; g < 8; g++) {
            uint32_t hw4[4], lw4[4];
            #pragma unroll
            for (int k = 0; k < 4; k++) {
                int q = g * 4 + k;
                ull v = fma2(ec2s[64 + q], f2p, ec2s[96 + q]);
                v = fma2(ec2s[32 + q], f1p, v);
                v = fma2(ec2s[q], f0p, v);
                float lo, hi; unpack2(v, lo, hi);
                lo = fmaxf(lo, 0.f); hi = fmaxf(hi, 0.f);
                split_pair(lo, hi, hw4[k], lw4[k]);
            }
            uint32_t off = SMEM_SWZ(rowbase + g * 16);
            *(uint4*)(Ahi + off) = make_uint4(hw4[0], hw4[1], hw4[2], hw4[3]);
            *(uint4*)(Alo + off) = make_uint4(lw4[0], lw4[1], lw4[2], lw4[3]);
        }
        __syncwarp();

        #pragma unroll
        for (int mt = 0; mt < 2; mt++) {
            int Rloc = wid * 32 + mt * 16;
            uint32_t ahi[4][4], alo[4][4];
            uint32_t arow = (uint32_t)(Rloc + l + ((sel & 1) << 3));
            #pragma unroll
            for (int kt = 0; kt < 4; kt++) {
                uint32_t acol = kt * 32 + ((sel & 2) ? 16 : 0);
                uint32_t aoff = SMEM_SWZ(arow * 128 + acol);
                ldmx4(ahi[kt][0], ahi[kt][1], ahi[kt][2], ahi[kt][3], AhiB + aoff);
                ldmx4(alo[kt][0], alo[kt][1], alo[kt][2], alo[kt][3], AloB + aoff);
            }

            float acc[8][4];
            #pragma unroll
            for (int nt = 0; nt < 8; nt++)
                #pragma unroll
                for (int c = 0; c < 4; c++) acc[nt][c] = 0.f;

            uint32_t wrow_l = (uint32_t)(l + ((sel & 2) ? 8 : 0));
            #pragma unroll
            for (int ntp = 0; ntp < 4; ntp++) {
                int nt0 = 2 * ntp, nt1 = 2 * ntp + 1;
                uint32_t wrow = (uint32_t)(ntp * 16) + wrow_l;
                #pragma unroll
                for (int kt = 0; kt < 4; kt++) {
                    uint32_t wcol = kt * 32 + ((sel & 1) ? 16 : 0);
                    uint32_t woff = SMEM_SWZ(wrow * 128 + wcol);
                    uint32_t wh0, wh1, wh2, wh3, wl0, wl1, wl2, wl3;
                    ldmx4(wh0, wh1, wh2, wh3, WhiB + woff);
                    ldmx4(wl0, wl1, wl2, wl3, WloB + woff);
                    mma_bf16(acc[nt0], ahi[kt], wh0, wh1);
                    mma_bf16(acc[nt1], ahi[kt], wh2, wh3);
                    mma_bf16(acc[nt0], alo[kt], wh0, wh1);
                    mma_bf16(acc[nt1], alo[kt], wh2, wh3);
                    mma_bf16(acc[nt0], ahi[kt], wl0, wl1);
                    mma_bf16(acc[nt1], ahi[kt], wl2, wl3);
                }
            }

            int g = lane >> 2, q = lane & 3;
            float p0 = 0.f, p1 = 0.f;
            #pragma unroll
            for (int nt = 0; nt < 8; nt++) {
                int c0 = nt * 8 + q * 2;
                float bb0 = b1s[c0], bb1 = b1s[c0 + 1];
                float ww0 = w2s[c0], ww1 = w2s[c0 + 1];
                p0 += ww0 * fmaxf(acc[nt][0] + bb0, 0.f)
                    + ww1 * fmaxf(acc[nt][1] + bb1, 0.f);
                p1 += ww0 * fmaxf(acc[nt][2] + bb0, 0.f)
                    + ww1 * fmaxf(acc[nt][3] + bb1, 0.f);
            }
            p0 += __shfl_xor_sync(0xffffffffu, p0, 1);
            p0 += __shfl_xor_sync(0xffffffffu, p0, 2);
            p1 += __shfl_xor_sync(0xffffffffu, p1, 1);
            p1 += __shfl_xor_sync(0xffffffffu, p1, 2);
            if (q == 0) {
                int er0 = wt * 32 + mt * 16 + g;
                int er1 = er0 + 8;
                if (er0 < E_) out[er0] = b2s + p0;
                if (er1 < E_) out[er1] = b2s + p1;
            }
        }
        __syncwarp();
    }
}

// ---------------- exclusive scan of g_cnt (4 elems/thread, int4) ------------
__global__ __launch_bounds__(1024) void k_scan(int N_) {
    __shared__ int warpsum[32];
    __shared__ int warpoff[32];
    __shared__ int carry_s;
    int t = threadIdx.x, lane = t & 31, wid = t >> 5;
    if (t == 0) carry_s = 0;
    __syncthreads();
    for (int base = 0; base < N_; base += 4096) {
        int i0 = base + t * 4;
        int v0 = 0, v1 = 0, v2 = 0, v3 = 0;
        if (i0 + 3 < N_) {
            int4 q = *(const int4*)&g_cnt[i0];
            v0 = q.x; v1 = q.y; v2 = q.z; v3 = q.w;
        } else {
            if (i0 < N_)     v0 = g_cnt[i0];
            if (i0 + 1 < N_) v1 = g_cnt[i0 + 1];
            if (i0 + 2 < N_) v2 = g_cnt[i0 + 2];
            if (i0 + 3 < N_) v3 = g_cnt[i0 + 3];
        }
        int sum = v0 + v1 + v2 + v3;
        int incl = sum;
        #pragma unroll
        for (int off = 1; off < 32; off <<= 1) {
            int x = __shfl_up_sync(0xffffffffu, incl, off);
            if (lane >= off) incl += x;
        }
        if (lane == 31) warpsum[wid] = incl;
        __syncthreads();
        if (wid == 0) {
            int s = warpsum[lane];
            int si = s;
            #pragma unroll
            for (int off = 1; off < 32; off <<= 1) {
                int x = __shfl_up_sync(0xffffffffu, si, off);
                if (lane >= off) si += x;
            }
            warpoff[lane] = si - s;
        }
        __syncthreads();
        int o0 = incl - sum + warpoff[wid] + carry_s;
        int o1 = o0 + v0, o2 = o1 + v1, o3 = o2 + v2;
        if (i0 + 3 < N_) {
            *(int4*)&g_off[i0] = make_int4(o0, o1, o2, o3);
            *(int4*)&g_cur[i0] = make_int4(o0, o1, o2, o3);
        } else {
            if (i0 < N_)     { g_off[i0] = o0;     g_cur[i0] = o0; }
            if (i0 + 1 < N_) { g_off[i0 + 1] = o1; g_cur[i0 + 1] = o1; }
            if (i0 + 2 < N_) { g_off[i0 + 2] = o2; g_cur[i0 + 2] = o2; }
            if (i0 + 3 < N_) { g_off[i0 + 3] = o3; g_cur[i0 + 3] = o3; }
        }
        __syncthreads();
        if (t == 0) carry_s += warpoff[31] + warpsum[31];
        __syncthreads();
    }
}

// ---------------- CSR fill: adj grouped by src (2 edges/thread) --------------
__global__ void k_fill(const int* __restrict__ ei, int E_) {
    int e = (blockIdx.x * blockDim.x + threadIdx.x) * 2;
    if (e >= E_) return;
    int s0 = ei[e], d0 = ei[E_ + e];
    int p0 = atomicAdd(&g_cur[s0], 1);
    g_adj[p0] = d0;
    if (e + 1 < E_) {
        int s1 = ei[e + 1], d1 = ei[E_ + e + 1];
        int p1 = atomicAdd(&g_cur[s1], 1);
        g_adj[p1] = d1;
    }
}

// ---------------- gather aggregation: 16 lanes/node, float4, unroll 4 --------
__global__ void k_agg(int which, int N_) {
    const float4* hin4 = (const float4*)(which ? g_hB : g_hA);
    int gid = blockIdx.x * blockDim.x + threadIdx.x;
    int node = gid >> 4, lane = gid & 15;
    if (node >= N_) return;
    int beg = g_off[node], cnt = g_cnt[node];
    int end = beg + cnt;
    float4 a0 = make_float4(0.f, 0.f, 0.f, 0.f);
    float4 a1 = a0, a2 = a0, a3 = a0;
    int i = beg;
    for (; i + 4 <= end; i += 4) {
        int d0 = g_adj[i], d1 = g_adj[i + 1], d2 = g_adj[i + 2], d3 = g_adj[i + 3];
        float4 v0 = hin4[d0 * 16 + lane];
        float4 v1 = hin4[d1 * 16 + lane];
        float4 v2 = hin4[d2 * 16 + lane];
        float4 v3 = hin4[d3 * 16 + lane];
        a0.x += v0.x; a0.y += v0.y; a0.z += v0.z; a0.w += v0.w;
        a1.x += v1.x; a1.y += v1.y; a1.z += v1.z; a1.w += v1.w;
        a2.x += v2.x; a2.y += v2.y; a2.z += v2.z; a2.w += v2.w;
        a3.x += v3.x; a3.y += v3.y; a3.z += v3.z; a3.w += v3.w;
    }
    for (; i < end; i++) {
        int d = g_adj[i];
        float4 v = hin4[d * 16 + lane];
        a0.x += v.x; a0.y += v.y; a0.z += v.z; a0.w += v.w;
    }
    float rd = (cnt > 0) ? 1.f / (float)cnt : 0.f;
    float4 o;
    o.x = (a0.x + a1.x + a2.x + a3.x) * rd;
    o.y = (a0.y + a1.y + a2.y + a3.y) * rd;
    o.z = (a0.z + a1.z + a2.z + a3.z) * rd;
    o.w = (a0.w + a1.w + a2.w + a3.w) * rd;
    ((float4*)g_neigh)[node * 16 + lane] = o;
}

// ---------------- SAGE combine (persistent): h = relu(Wself@h + Wneigh@mean + b)
__global__ void k_combine(const float* __restrict__ Wself, const float* __restrict__ bself,
                          const float* __restrict__ Wneigh, const float* __restrict__ bneigh,
                          float* hout, int which_in, int use_hout, int N_) {
    const float* hin = which_in ? g_hB : g_hA;
    __shared__ float4 WsA[16 * H];  // [kg][j]
    __shared__ float4 WnA[16 * H];
    __shared__ float4 hs4[4][16];
    __shared__ float4 ns4[4][16];
    int tx = threadIdx.x, ty = threadIdx.y;
    int t = ty * 64 + tx;
    const float4* gs = (const float4*)Wself;
    const float4* gn = (const float4*)Wneigh;
    for (int i = t; i < H * 16; i += 256) {
        int j = i >> 4, kg = i & 15;
        WsA[kg * H + j] = gs[i];
        WnA[kg * H + j] = gn[i];
    }
    float bias = bself[tx] + bneigh[tx];
    float* o = use_hout ? hout : g_hB;
    int ntiles = (N_ + 3) / 4;
    for (int tile = blockIdx.x; tile < ntiles; tile += gridDim.x) {
        __syncthreads();
        int n = tile * 4 + ty;
        if (n < N_) {
            ((float*)hs4)[t] = hin[(size_t)n * H + tx];
            ((float*)ns4)[t] = g_neigh[(size_t)n * H + tx];
        }
        __syncthreads();
        if (n < N_) {
            float acc = bias;
            #pragma unroll
            for (int kg = 0; kg < 16; kg++) {
                float4 hv = hs4[ty][kg];
                float4 nv = ns4[ty][kg];
                float4 ws = WsA[kg * H + tx];
                float4 wn = WnA[kg * H + tx];
                acc += hv.x * ws.x + hv.y * ws.y + hv.z * ws.z + hv.w * ws.w
                     + nv.x * wn.x + nv.y * wn.y + nv.z * wn.z + nv.w * wn.w;
            }
            o[(size_t)n * H + tx] = fmaxf(acc, 0.f);
        }
    }
}

// ---------------- launch ----------------
extern "C" void kernel_launch(void* const* d_in, const int* in_sizes, int n_in,
                              void* d_out, int out_size) {
    const float* node_feats = (const float*)d_in[0];
    const float* edge_feats = (const float*)d_in[1];
    const float* enc        = (const float*)d_in[2];
    const int*   ei         = (const int*)d_in[3];
    const float* Wn     = (const float*)d_in[4];
    const float* bn     = (const float*)d_in[5];
    const float* We     = (const float*)d_in[6];
    const float* be     = (const float*)d_in[7];
    const float* Wself  = (const float*)d_in[8];   // (2,64,64)
    const float* bself  = (const float*)d_in[9];   // (2,64)
    const float* Wneigh = (const float*)d_in[10];
    const float* bneigh = (const float*)d_in[11];
    const float* Wa     = (const float*)d_in[12];
    const float* ba     = (const float*)d_in[13];
    const float* W1     = (const float*)d_in[14];
    const float* b1     = (const float*)d_in[15];
    const float* W2     = (const float*)d_in[16];
    const float* b2     = (const float*)d_in[17];

    int N_ = in_sizes[0] / 3;
    int E_ = in_sizes[1] / 3;
    float* out = (float*)d_out;
    float* h_out = out + E_;  // output = [scores (E), h (N*64)]

    int n64 = N_ * H;
    dim3 cdim(64, 4);
    int cgrid = 888;
    int agrid = (N_ * 16 + 255) / 256;          // 16 lanes per node

    int wtiles = (E_ + 31) / 32;
    int sgrid = (wtiles + 3) / 4;
    if (sgrid > 592) sgrid = 592;               // 4 persistent CTAs/SM
    int dyn_smem = 50176;
    cudaFuncSetAttribute(k_scorer_mma,
                         cudaFuncAttributeMaxDynamicSharedMemorySize, dyn_smem);

    // 1. fused init: pre + nodefc + cnt zero
    k_init<<<1 + (n64 + 255) / 256, 256>>>(node_feats, Wn, bn, enc, Wa, ba, We, be, N_);
    // 2. tensor-core edge scorer (counts degrees) -> out[0:E]
    k_scorer_mma<<<sgrid, 128, dyn_smem>>>(edge_feats, ei, W1, b1, W2, b2, out, E_);
    // 3. CSR build
    k_scan<<<1, 1024>>>(N_);
    k_fill<<<(E_ / 2 + 255) / 256, 256>>>(ei, E_);
    // 4. layer 0
    k_agg<<<agrid, 256>>>(0, N_);
    k_combine<<<cgrid, cdim>>>(Wself, bself, Wneigh, bneigh, nullptr, 0, 0, N_);
    // 5. layer 1
    k_agg<<<agrid, 256>>>(1, N_);
    k_combine<<<cgrid, cdim>>>(Wself + H * H, bself + H,
                               Wneigh + H * H, bneigh + H,
                               h_out, 1, 1, N_);
}